// round 1
// baseline (speedup 1.0000x reference)
#include <cuda_runtime.h>
#include <cstdint>

#define NNODE 20000
#define FEAT  512
#define EMAX  320000
#define FF    (FEAT*FEAT)
#define BN_EPS 1e-5f

// ---------------- device scratch (no allocs allowed) ----------------
__device__ float g_hd [NNODE*FEAT];
__device__ float g_hp [NNODE*FEAT];
__device__ float g_hd2[NNODE*FEAT];
__device__ float g_hp2[NNODE*FEAT];
__device__ float g_mean[NNODE*FEAT];
__device__ float g_Wsum[FF];
__device__ float g_bsum[FEAT];
__device__ float g_bnstat[2*FEAT];
__device__ int   g_cnt[4*NNODE];
__device__ int   g_cur[4*NNODE];
__device__ int   g_off[4*(NNODE+1)];
__device__ int   g_adj[4*EMAX];

// ---------------- f32x2 packed helpers ----------------
__device__ __forceinline__ unsigned long long pk2(float x) {
    unsigned long long r;
    asm("mov.b64 %0, {%1, %1};" : "=l"(r) : "r"(__float_as_uint(x)));
    return r;
}
__device__ __forceinline__ unsigned long long ffma2(unsigned long long a,
                                                    unsigned long long b,
                                                    unsigned long long c) {
    unsigned long long d;
    asm("fma.rn.f32x2 %0, %1, %2, %3;" : "=l"(d) : "l"(a), "l"(b), "l"(c));
    return d;
}
__device__ __forceinline__ void upk(unsigned long long v, float& lo, float& hi) {
    unsigned int a, b;
    asm("mov.b64 {%0, %1}, %2;" : "=r"(a), "=r"(b) : "l"(v));
    lo = __uint_as_float(a);
    hi = __uint_as_float(b);
}

// ---------------- CSR build ----------------
__global__ void zero_cnt_kernel() {
    int i = blockIdx.x * blockDim.x + threadIdx.x;
    if (i < 4 * NNODE) g_cnt[i] = 0;
}

__global__ void hist_kernel(const int* __restrict__ a_src, const int* __restrict__ a_dst,
                            const int* __restrict__ i_src, const int* __restrict__ i_dst, int E) {
    int i = blockIdx.x * blockDim.x + threadIdx.x;
    if (i >= 4 * E) return;
    int w = i / E, e = i - w * E;
    int k = (w == 0) ? a_dst[e] : (w == 1) ? a_src[e] : (w == 2) ? i_dst[e] : i_src[e];
    atomicAdd(&g_cnt[w * NNODE + k], 1);
}

__global__ void scan_kernel() {
    int c = blockIdx.x;           // which CSR
    __shared__ int sh[1024];
    __shared__ int carry_sh;
    int tid = threadIdx.x;
    if (tid == 0) { carry_sh = 0; g_off[c * (NNODE + 1)] = 0; }
    __syncthreads();
    for (int base = 0; base < NNODE; base += 1024) {
        int i = base + tid;
        int v = (i < NNODE) ? g_cnt[c * NNODE + i] : 0;
        sh[tid] = v;
        __syncthreads();
        #pragma unroll
        for (int d = 1; d < 1024; d <<= 1) {
            int t = (tid >= d) ? sh[tid - d] : 0;
            __syncthreads();
            sh[tid] += t;
            __syncthreads();
        }
        int incl = sh[tid];
        int carry = carry_sh;
        __syncthreads();
        if (i < NNODE) {
            g_off[c * (NNODE + 1) + i + 1] = carry + incl;
            g_cur[c * NNODE + i] = carry + incl - v;  // exclusive: fill cursor
        }
        if (tid == 1023) carry_sh = carry + sh[1023];
        __syncthreads();
    }
}

__global__ void fill_kernel(const int* __restrict__ a_src, const int* __restrict__ a_dst,
                            const int* __restrict__ i_src, const int* __restrict__ i_dst, int E) {
    int i = blockIdx.x * blockDim.x + threadIdx.x;
    if (i >= 4 * E) return;
    int w = i / E, e = i - w * E;
    int k = (w == 0) ? a_dst[e] : (w == 1) ? a_src[e] : (w == 2) ? i_dst[e] : i_src[e];
    int v = (w == 0) ? a_src[e] : (w == 1) ? a_dst[e] : (w == 2) ? i_src[e] : i_dst[e];
    int pos = atomicAdd(&g_cur[w * NNODE + k], 1);
    g_adj[w * E + pos] = v;
}

// ---------------- segment mean via CSR gather (deterministic, no float atomics) ----------------
__global__ void gather_mean_kernel(const float* __restrict__ src, int c, int E) {
    int n = blockIdx.x;        // dst node
    int t = threadIdx.x;       // 128 threads, 4 floats each
    int s = g_off[c * (NNODE + 1) + n];
    int e = g_off[c * (NNODE + 1) + n + 1];
    const int* adj = g_adj + (size_t)c * E;
    float4 acc = make_float4(0.f, 0.f, 0.f, 0.f);
    int j = s;
    for (; j + 1 < e; j += 2) {
        int r0 = adj[j], r1 = adj[j + 1];
        float4 v0 = *(const float4*)(src + (size_t)r0 * FEAT + t * 4);
        float4 v1 = *(const float4*)(src + (size_t)r1 * FEAT + t * 4);
        acc.x += v0.x + v1.x; acc.y += v0.y + v1.y;
        acc.z += v0.z + v1.z; acc.w += v0.w + v1.w;
    }
    if (j < e) {
        int r0 = adj[j];
        float4 v0 = *(const float4*)(src + (size_t)r0 * FEAT + t * 4);
        acc.x += v0.x; acc.y += v0.y; acc.z += v0.z; acc.w += v0.w;
    }
    float inv = (e > s) ? 1.0f / (float)(e - s) : 0.0f;
    acc.x *= inv; acc.y *= inv; acc.z *= inv; acc.w *= inv;
    *(float4*)(g_mean + (size_t)n * FEAT + t * 4) = acc;
}

// ---------------- weight fusion: Wsum = Ws0+Ws2+Ws3, bsum = b0+b2+b3 ----------------
__global__ void wsum_kernel(const float* __restrict__ Ws, const float* __restrict__ b) {
    int i = blockIdx.x * blockDim.x + threadIdx.x;
    if (i < FF)   g_Wsum[i] = Ws[i] + Ws[2 * FF + i] + Ws[3 * FF + i];
    if (i < FEAT) g_bsum[i] = b[i] + b[2 * FEAT + i] + b[3 * FEAT + i];
}

// ---------------- SGEMM: C[M,512] = A[M,512] @ B[512,512] (+bias | +=C) ----------------
// 128x128 tile, BK=8, 256 threads, 8x8 per thread, f32x2 packed FFMA inner product.
template <int MODE>  // 0: C = A@B + bias ; 1: C += A@B
__global__ __launch_bounds__(256, 2)
void sgemm_kernel(const float* __restrict__ A, const float* __restrict__ B,
                  const float* __restrict__ bias, float* __restrict__ C, int M) {
    const int N = FEAT, K = FEAT;
    __shared__ float As[2][8][128];   // [buf][k][m]
    __shared__ float Bs[2][8][128];   // [buf][k][n]
    int tid = threadIdx.x;
    int m0 = blockIdx.y * 128;
    int n0 = blockIdx.x * 128;
    int aRow = tid >> 1;              // 0..127
    int aK   = (tid & 1) * 4;         // 0 or 4
    int bRow = tid >> 5;              // 0..7
    int bCol = (tid & 31) * 4;        // 0..124
    int tr = (tid >> 4) * 8;          // thread row base
    int tc = (tid & 15) * 8;          // thread col base

    unsigned long long acc[8][4];
    #pragma unroll
    for (int i = 0; i < 8; i++)
        #pragma unroll
        for (int j = 0; j < 4; j++) acc[i][j] = 0ULL;

    float4 aReg, bReg;
    {
        int gr = m0 + aRow;
        aReg = (gr < M) ? *(const float4*)(A + (size_t)gr * K + aK)
                        : make_float4(0.f, 0.f, 0.f, 0.f);
        bReg = *(const float4*)(B + (size_t)bRow * N + n0 + bCol);
    }
    As[0][aK + 0][aRow] = aReg.x; As[0][aK + 1][aRow] = aReg.y;
    As[0][aK + 2][aRow] = aReg.z; As[0][aK + 3][aRow] = aReg.w;
    *(float4*)&Bs[0][bRow][bCol] = bReg;
    __syncthreads();

    int buf = 0;
    const int NT = K / 8;  // 64
    for (int t = 0; t < NT; ++t) {
        if (t + 1 < NT) {
            int k0 = (t + 1) * 8;
            int gr = m0 + aRow;
            aReg = (gr < M) ? *(const float4*)(A + (size_t)gr * K + k0 + aK)
                            : make_float4(0.f, 0.f, 0.f, 0.f);
            bReg = *(const float4*)(B + (size_t)(k0 + bRow) * N + n0 + bCol);
        }
        #pragma unroll
        for (int kk = 0; kk < 8; ++kk) {
            float4 a0 = *(const float4*)&As[buf][kk][tr];
            float4 a1 = *(const float4*)&As[buf][kk][tr + 4];
            ulonglong2 bp0 = *(const ulonglong2*)&Bs[buf][kk][tc];
            ulonglong2 bp1 = *(const ulonglong2*)&Bs[buf][kk][tc + 4];
            unsigned long long bb[4] = {bp0.x, bp0.y, bp1.x, bp1.y};
            float av[8] = {a0.x, a0.y, a0.z, a0.w, a1.x, a1.y, a1.z, a1.w};
            #pragma unroll
            for (int i = 0; i < 8; i++) {
                unsigned long long ad = pk2(av[i]);
                #pragma unroll
                for (int j = 0; j < 4; j++) acc[i][j] = ffma2(ad, bb[j], acc[i][j]);
            }
        }
        if (t + 1 < NT) {
            int nb = buf ^ 1;
            As[nb][aK + 0][aRow] = aReg.x; As[nb][aK + 1][aRow] = aReg.y;
            As[nb][aK + 2][aRow] = aReg.z; As[nb][aK + 3][aRow] = aReg.w;
            *(float4*)&Bs[nb][bRow][bCol] = bReg;
            __syncthreads();
            buf = nb;
        }
    }

    float bcol[8];
    if (MODE == 0) {
        #pragma unroll
        for (int j = 0; j < 8; j++) bcol[j] = bias[n0 + tc + j];
    }
    #pragma unroll
    for (int i = 0; i < 8; i++) {
        int gr = m0 + tr + i;
        if (gr < M) {
            float v[8];
            #pragma unroll
            for (int j = 0; j < 4; j++) { upk(acc[i][j], v[2 * j], v[2 * j + 1]); }
            float* cp = C + (size_t)gr * N + n0 + tc;
            if (MODE == 0) {
                #pragma unroll
                for (int j = 0; j < 8; j++) v[j] += bcol[j];
                *(float4*)cp       = make_float4(v[0], v[1], v[2], v[3]);
                *(float4*)(cp + 4) = make_float4(v[4], v[5], v[6], v[7]);
            } else {
                float4 c0 = *(float4*)cp, c1 = *(float4*)(cp + 4);
                *(float4*)cp       = make_float4(v[0] + c0.x, v[1] + c0.y, v[2] + c0.z, v[3] + c0.w);
                *(float4*)(cp + 4) = make_float4(v[4] + c1.x, v[5] + c1.y, v[6] + c1.z, v[7] + c1.w);
            }
        }
    }
}

// ---------------- BatchNorm + ReLU ----------------
__global__ void zero_stats_kernel() {
    int i = threadIdx.x;
    if (i < 2 * FEAT) g_bnstat[i] = 0.f;
}

__global__ void bn_reduce_kernel(const float* __restrict__ x) {
    int col = blockIdx.x * 256 + threadIdx.x;   // grid.x = 2
    float s = 0.f, s2 = 0.f;
    for (int r = blockIdx.y; r < NNODE; r += gridDim.y) {
        float v = x[(size_t)r * FEAT + col];
        s += v; s2 += v * v;
    }
    atomicAdd(&g_bnstat[col], s);
    atomicAdd(&g_bnstat[FEAT + col], s2);
}

__global__ void bn_norm_kernel(float* __restrict__ x,
                               const float* __restrict__ gamma,
                               const float* __restrict__ beta) {
    size_t idx = (size_t)blockIdx.x * blockDim.x + threadIdx.x;
    if (idx >= (size_t)NNODE * FEAT) return;
    int col = (int)(idx & (FEAT - 1));
    float mean = g_bnstat[col] * (1.0f / NNODE);
    float var  = g_bnstat[FEAT + col] * (1.0f / NNODE) - mean * mean;
    float sc = gamma[col] * rsqrtf(var + BN_EPS);
    float v = (x[idx] - mean) * sc + beta[col];
    x[idx] = v > 0.f ? v : 0.f;
}

// ---------------- host orchestration ----------------
static void run_layer(const float* hd_in, const float* hp_in,
                      float* hd_out, float* hp_out,
                      const float* Ws, const float* Wn, const float* b,
                      const float* gamma, const float* beta,
                      float* mean, float* Wsum, float* bsum, int E) {
    dim3 gg(FEAT / 128, (NNODE + 127) / 128);

    wsum_kernel<<<(FF + 255) / 256, 256>>>(Ws, b);
    // protein: self (fused) + 3 neighbor terms
    sgemm_kernel<0><<<gg, 256>>>(hp_in, Wsum, bsum, hp_out, NNODE);
    gather_mean_kernel<<<NNODE, 128>>>(hd_in, 0, E);                // associates: d->p
    sgemm_kernel<1><<<gg, 256>>>(mean, Wn + 0 * FF, nullptr, hp_out, NNODE);
    gather_mean_kernel<<<NNODE, 128>>>(hp_in, 2, E);                // interacts: p->p
    sgemm_kernel<1><<<gg, 256>>>(mean, Wn + 2 * FF, nullptr, hp_out, NNODE);
    gather_mean_kernel<<<NNODE, 128>>>(hp_in, 3, E);                // rev_interacts
    sgemm_kernel<1><<<gg, 256>>>(mean, Wn + 3 * FF, nullptr, hp_out, NNODE);
    // disease: self + neighbor (rev_associates: p->d)
    sgemm_kernel<0><<<gg, 256>>>(hd_in, Ws + 1 * FF, b + FEAT, hd_out, NNODE);
    gather_mean_kernel<<<NNODE, 128>>>(hp_in, 1, E);
    sgemm_kernel<1><<<gg, 256>>>(mean, Wn + 1 * FF, nullptr, hd_out, NNODE);
    // BN + ReLU (disease = ntype 0, protein = ntype 1)
    zero_stats_kernel<<<1, 1024>>>();
    bn_reduce_kernel<<<dim3(2, 64), 256>>>(hd_out);
    bn_norm_kernel<<<(NNODE * FEAT + 255) / 256, 256>>>(hd_out, gamma, beta);
    zero_stats_kernel<<<1, 1024>>>();
    bn_reduce_kernel<<<dim3(2, 64), 256>>>(hp_out);
    bn_norm_kernel<<<(NNODE * FEAT + 255) / 256, 256>>>(hp_out, gamma + FEAT, beta + FEAT);
}

extern "C" void kernel_launch(void* const* d_in, const int* in_sizes, int n_in,
                              void* d_out, int out_size) {
    const float* h_d  = (const float*)d_in[0];
    const float* h_p  = (const float*)d_in[1];
    const float* Ws1  = (const float*)d_in[2];
    const float* Wn1  = (const float*)d_in[3];
    const float* b1   = (const float*)d_in[4];
    const float* Ws2  = (const float*)d_in[5];
    const float* Wn2  = (const float*)d_in[6];
    const float* b2   = (const float*)d_in[7];
    const float* gam  = (const float*)d_in[8];
    const float* bet  = (const float*)d_in[9];
    const float* pWd  = (const float*)d_in[10];
    const float* pbd  = (const float*)d_in[11];
    const float* pWp  = (const float*)d_in[12];
    const float* pbp  = (const float*)d_in[13];
    const int*   a_src = (const int*)d_in[14];
    const int*   a_dst = (const int*)d_in[15];
    const int*   i_src = (const int*)d_in[16];
    const int*   i_dst = (const int*)d_in[17];
    int E = in_sizes[14];

    float* out_d = (float*)d_out;
    float* out_p = out_d + (size_t)NNODE * FEAT;

    float *hd, *hp, *hd2, *hp2, *mean, *Wsum, *bsum;
    cudaGetSymbolAddress((void**)&hd,   g_hd);
    cudaGetSymbolAddress((void**)&hp,   g_hp);
    cudaGetSymbolAddress((void**)&hd2,  g_hd2);
    cudaGetSymbolAddress((void**)&hp2,  g_hp2);
    cudaGetSymbolAddress((void**)&mean, g_mean);
    cudaGetSymbolAddress((void**)&Wsum, g_Wsum);
    cudaGetSymbolAddress((void**)&bsum, g_bsum);

    // Build 4 CSRs: 0: key a_dst / val a_src (gather hd)
    //               1: key a_src / val a_dst (gather hp)
    //               2: key i_dst / val i_src (gather hp)
    //               3: key i_src / val i_dst (gather hp)
    zero_cnt_kernel<<<(4 * NNODE + 255) / 256, 256>>>();
    hist_kernel<<<(4 * E + 255) / 256, 256>>>(a_src, a_dst, i_src, i_dst, E);
    scan_kernel<<<4, 1024>>>();
    fill_kernel<<<(4 * E + 255) / 256, 256>>>(a_src, a_dst, i_src, i_dst, E);

    // layer 1: inputs -> (g_hd, g_hp)
    run_layer(h_d, h_p, hd, hp, Ws1, Wn1, b1, gam, bet, mean, Wsum, bsum, E);
    // layer 2: (g_hd, g_hp) -> (g_hd2, g_hp2)
    run_layer(hd, hp, hd2, hp2, Ws2, Wn2, b2, gam + 2 * FEAT, bet + 2 * FEAT,
              mean, Wsum, bsum, E);

    // projections
    dim3 gg(FEAT / 128, (NNODE + 127) / 128);
    sgemm_kernel<0><<<gg, 256>>>(hd2, pWd, pbd, out_d, NNODE);
    sgemm_kernel<0><<<gg, 256>>>(hp2, pWp, pbp, out_p, NNODE);
}

// round 3
// speedup vs baseline: 1.9445x; 1.9445x over previous
#include <cuda_runtime.h>
#include <cuda_bf16.h>
#include <cstdint>

#define NNODE 20000
#define MPAD  20096
#define FEAT  512
#define EMAX  320000
#define FF    (FEAT*FEAT)
#define BN_EPS 1e-5f

// Feature gate: tcgen05 only exists in the arch-specific (sm_103a/sm_100a) pass.
#if defined(__CUDA_ARCH_FEAT_SM103_ALL) || defined(__CUDA_ARCH_FEAT_SM100_ALL) || defined(__CUDA_ARCH_FEAT_SM101_ALL)
#define HAS_TCGEN05 1
#else
#define HAS_TCGEN05 0
#endif

// ================= device scratch (static, no allocs) =================
__device__ __nv_bfloat16 g_Ap_hi[(size_t)MPAD * 2048];
__device__ __nv_bfloat16 g_Ap_lo[(size_t)MPAD * 2048];
__device__ __nv_bfloat16 g_Ad_hi[(size_t)MPAD * 1024];
__device__ __nv_bfloat16 g_Ad_lo[(size_t)MPAD * 1024];
__device__ __nv_bfloat16 g_Bp_hi[512 * 2048];
__device__ __nv_bfloat16 g_Bp_lo[512 * 2048];
__device__ __nv_bfloat16 g_Bd_hi[512 * 1024];
__device__ __nv_bfloat16 g_Bd_lo[512 * 1024];
__device__ __nv_bfloat16 g_Bq_hi[2][512 * 512];
__device__ __nv_bfloat16 g_Bq_lo[2][512 * 512];
__device__ float g_biasP[FEAT];
__device__ float g_biasD[FEAT];
__device__ float g_rawd[(size_t)NNODE * FEAT];
__device__ float g_rawp[(size_t)NNODE * FEAT];
__device__ float g_hdf [(size_t)NNODE * FEAT];
__device__ float g_hpf [(size_t)NNODE * FEAT];
__device__ float g_bnstat[2 * FEAT];
__device__ int   g_cnt[4 * NNODE];
__device__ int   g_cur[4 * NNODE];
__device__ int   g_off[4 * (NNODE + 1)];
__device__ int   g_adj[4 * EMAX];

// ================= PTX helpers =================
__device__ __forceinline__ uint32_t smem_to_u32(const void* p) {
    uint32_t a;
    asm("{ .reg .u64 t; cvta.to.shared.u64 t, %1; cvt.u32.u64 %0, t; }" : "=r"(a) : "l"(p));
    return a;
}
__device__ __forceinline__ uint32_t elect_one_pred() {
    uint32_t pred;
    asm volatile("{\n\t.reg .pred p;\n\telect.sync _|p, 0xFFFFFFFF;\n\tselp.b32 %0, 1, 0, p;\n\t}" : "=r"(pred));
    return pred;
}
#define SMEM_SWIZZLE_128B(o) ((o) ^ (((o) >> 3) & 0x70))
static constexpr uint64_t SMEM_DESC_BASE_SW128 =
    (uint64_t(2) << 61) | (uint64_t(1) << 46) | (uint64_t(64) << 32) | (uint64_t(1) << 16);
#define MAKE_SMEM_DESC(base) (SMEM_DESC_BASE_SW128 | ((uint64_t)((base) >> 4) & 0x3FFF))

#if HAS_TCGEN05
#define TCGEN05_ALLOC(sm, n) \
    asm volatile("tcgen05.alloc.cta_group::1.sync.aligned.shared::cta.b32 [%0], %1;" \
                 :: "r"((uint32_t)(sm)), "r"((uint32_t)(n)) : "memory")
#define TCGEN05_DEALLOC(t, n) \
    asm volatile("tcgen05.dealloc.cta_group::1.sync.aligned.b32 %0, %1;" :: "r"(t), "r"((uint32_t)(n)))
#define TCGEN05_RELINQ() \
    asm volatile("tcgen05.relinquish_alloc_permit.cta_group::1.sync.aligned;")
#define TCGEN05_COMMIT(mb) \
    asm volatile("tcgen05.commit.cta_group::1.mbarrier::arrive::one.shared::cluster.b64 [%0];" \
                 :: "r"((uint32_t)(mb)) : "memory")
#define TCGEN05_WAIT_LD()  asm volatile("tcgen05.wait::ld.sync.aligned;" ::: "memory")
#define TCGEN05_FENCE_BEFORE() asm volatile("tcgen05.fence::before_thread_sync;" ::: "memory")
#define TCGEN05_FENCE_AFTER()  asm volatile("tcgen05.fence::after_thread_sync;" ::: "memory")
#define FENCE_ASYNC_SHARED() asm volatile("fence.proxy.async.shared::cta;" ::: "memory")
#define MBARRIER_INIT(mb, c) \
    asm volatile("mbarrier.init.shared.b64 [%0], %1;" :: "r"((uint32_t)(mb)), "r"((uint32_t)(c)) : "memory")
#define MBARRIER_INVAL(mb) \
    asm volatile("mbarrier.inval.shared.b64 [%0];" :: "r"((uint32_t)(mb)) : "memory")
#define MBARRIER_WAIT_PARITY(mb, ph) do { \
    uint32_t _mb = (uint32_t)(mb), _ph = (uint32_t)(ph), _done; \
    asm volatile("{\n\t.reg .pred p;\n\tmbarrier.try_wait.parity.acquire.cta.shared::cta.b64 p, [%1], %2;\n\tselp.b32 %0, 1, 0, p;\n\t}" \
        : "=r"(_done) : "r"(_mb), "r"(_ph) : "memory"); \
    if (!_done) { \
        asm volatile("{\n\t.reg .pred P1;\n\tWL_%=: \n\tmbarrier.try_wait.parity.acquire.cta.shared::cta.b64 P1, [%0], %1, 0x989680;\n\t@P1 bra.uni WD_%=;\n\tbra.uni WL_%=;\n\tWD_%=: \n\t}" \
            :: "r"(_mb), "r"(_ph) : "memory"); \
    } \
} while (0)

#define TCGEN05_LD_X32(r, addr) \
    asm volatile("tcgen05.ld.sync.aligned.32x32b.x32.b32 " \
        "{%0, %1, %2, %3, %4, %5, %6, %7, %8, %9, %10, %11, %12, %13, %14, %15, " \
        " %16, %17, %18, %19, %20, %21, %22, %23, %24, %25, %26, %27, %28, %29, %30, %31}, [%32];" \
        : "=r"((r)[0]), "=r"((r)[1]), "=r"((r)[2]), "=r"((r)[3]), "=r"((r)[4]), "=r"((r)[5]), "=r"((r)[6]), "=r"((r)[7]), \
          "=r"((r)[8]), "=r"((r)[9]), "=r"((r)[10]), "=r"((r)[11]), "=r"((r)[12]), "=r"((r)[13]), "=r"((r)[14]), "=r"((r)[15]), \
          "=r"((r)[16]), "=r"((r)[17]), "=r"((r)[18]), "=r"((r)[19]), "=r"((r)[20]), "=r"((r)[21]), "=r"((r)[22]), "=r"((r)[23]), \
          "=r"((r)[24]), "=r"((r)[25]), "=r"((r)[26]), "=r"((r)[27]), "=r"((r)[28]), "=r"((r)[29]), "=r"((r)[30]), "=r"((r)[31]) \
        : "r"(addr))

__device__ __forceinline__ void mma_bf16_ss(uint32_t d_tmem, uint64_t a_desc, uint64_t b_desc,
                                            uint32_t idesc, uint32_t enable) {
    asm volatile(
        "{\n\t.reg .pred p;\n\tsetp.ne.u32 p, %5, 0;\n\t"
        "tcgen05.mma.cta_group::1.kind::f16 [%0], %1, %2, %3, {%4, %4, %4, %4}, p;\n\t}"
        :: "r"(d_tmem), "l"(a_desc), "l"(b_desc), "r"(idesc), "r"(0u), "r"(enable)
        : "memory");
}
#endif // HAS_TCGEN05

// split helpers
__device__ __forceinline__ void split1(float v, __nv_bfloat16& h, __nv_bfloat16& l) {
    h = __float2bfloat16(v);
    l = __float2bfloat16(v - __bfloat162float(h));
}

// ================= CSR build =================
__global__ void zero_cnt_kernel() {
    int i = blockIdx.x * blockDim.x + threadIdx.x;
    if (i < 4 * NNODE) g_cnt[i] = 0;
}
__global__ void hist_kernel(const int* __restrict__ a_src, const int* __restrict__ a_dst,
                            const int* __restrict__ i_src, const int* __restrict__ i_dst, int E) {
    int i = blockIdx.x * blockDim.x + threadIdx.x;
    if (i >= 4 * E) return;
    int w = i / E, e = i - w * E;
    int k = (w == 0) ? a_dst[e] : (w == 1) ? a_src[e] : (w == 2) ? i_dst[e] : i_src[e];
    atomicAdd(&g_cnt[w * NNODE + k], 1);
}
__global__ void scan_kernel() {
    int c = blockIdx.x;
    __shared__ int sh[1024];
    __shared__ int carry_sh;
    int tid = threadIdx.x;
    if (tid == 0) { carry_sh = 0; g_off[c * (NNODE + 1)] = 0; }
    __syncthreads();
    for (int base = 0; base < NNODE; base += 1024) {
        int i = base + tid;
        int v = (i < NNODE) ? g_cnt[c * NNODE + i] : 0;
        sh[tid] = v;
        __syncthreads();
        #pragma unroll
        for (int d = 1; d < 1024; d <<= 1) {
            int t = (tid >= d) ? sh[tid - d] : 0;
            __syncthreads();
            sh[tid] += t;
            __syncthreads();
        }
        int incl = sh[tid];
        int carry = carry_sh;
        __syncthreads();
        if (i < NNODE) {
            g_off[c * (NNODE + 1) + i + 1] = carry + incl;
            g_cur[c * NNODE + i] = carry + incl - v;
        }
        if (tid == 1023) carry_sh = carry + sh[1023];
        __syncthreads();
    }
}
__global__ void fill_kernel(const int* __restrict__ a_src, const int* __restrict__ a_dst,
                            const int* __restrict__ i_src, const int* __restrict__ i_dst, int E) {
    int i = blockIdx.x * blockDim.x + threadIdx.x;
    if (i >= 4 * E) return;
    int w = i / E, e = i - w * E;
    int k = (w == 0) ? a_dst[e] : (w == 1) ? a_src[e] : (w == 2) ? i_dst[e] : i_src[e];
    int v = (w == 0) ? a_src[e] : (w == 1) ? a_dst[e] : (w == 2) ? i_src[e] : i_dst[e];
    int pos = atomicAdd(&g_cur[w * NNODE + k], 1);
    g_adj[w * E + pos] = v;
}

// ========== segment mean via CSR gather → bf16 hi/lo splits into stacked A slots ==========
__global__ void gather_split_kernel(const float* __restrict__ src, int c, int E,
                                    __nv_bfloat16* __restrict__ hi, __nv_bfloat16* __restrict__ lo,
                                    int lda, int coff) {
    int n = blockIdx.x;
    int t = threadIdx.x;        // 128 threads, 4 floats each
    int s = g_off[c * (NNODE + 1) + n];
    int e = g_off[c * (NNODE + 1) + n + 1];
    const int* adj = g_adj + (size_t)c * E;
    float4 acc = make_float4(0.f, 0.f, 0.f, 0.f);
    int j = s;
    for (; j + 1 < e; j += 2) {
        int r0 = adj[j], r1 = adj[j + 1];
        float4 v0 = *(const float4*)(src + (size_t)r0 * FEAT + t * 4);
        float4 v1 = *(const float4*)(src + (size_t)r1 * FEAT + t * 4);
        acc.x += v0.x + v1.x; acc.y += v0.y + v1.y;
        acc.z += v0.z + v1.z; acc.w += v0.w + v1.w;
    }
    if (j < e) {
        int r0 = adj[j];
        float4 v0 = *(const float4*)(src + (size_t)r0 * FEAT + t * 4);
        acc.x += v0.x; acc.y += v0.y; acc.z += v0.z; acc.w += v0.w;
    }
    float inv = (e > s) ? 1.0f / (float)(e - s) : 0.0f;
    float v[4] = {acc.x * inv, acc.y * inv, acc.z * inv, acc.w * inv};
    size_t o = (size_t)n * lda + coff + t * 4;
    __nv_bfloat16 h[4], l[4];
    #pragma unroll
    for (int q = 0; q < 4; q++) split1(v[q], h[q], l[q]);
    *(__nv_bfloat162*)(hi + o)     = *(__nv_bfloat162*)&h[0];
    *(__nv_bfloat162*)(hi + o + 2) = *(__nv_bfloat162*)&h[2];
    *(__nv_bfloat162*)(lo + o)     = *(__nv_bfloat162*)&l[0];
    *(__nv_bfloat162*)(lo + o + 2) = *(__nv_bfloat162*)&l[2];
}

// ========== split fp32 matrix into stacked-A slot ==========
__global__ void split_input_kernel(const float* __restrict__ src,
                                   __nv_bfloat16* __restrict__ hi, __nv_bfloat16* __restrict__ lo,
                                   int lda, int coff) {
    size_t idx = (size_t)blockIdx.x * blockDim.x + threadIdx.x;
    if (idx >= (size_t)NNODE * FEAT) return;
    int row = (int)(idx >> 9), col = (int)(idx & 511);
    float v = src[idx];
    __nv_bfloat16 h, l;
    split1(v, h, l);
    size_t o = (size_t)row * lda + coff + col;
    hi[o] = h; lo[o] = l;
}

// ========== weight prep: transpose + fuse + split ==========
__global__ void wprep_p_kernel(const float* __restrict__ Ws, const float* __restrict__ Wn,
                               const float* __restrict__ b) {
    int i = blockIdx.x * blockDim.x + threadIdx.x;
    if (i >= FF) return;
    int n = i & 511, k = i >> 9;
    float v0 = Ws[k * 512 + n] + Ws[2 * FF + k * 512 + n] + Ws[3 * FF + k * 512 + n];
    float v1 = Wn[0 * FF + k * 512 + n];
    float v2 = Wn[2 * FF + k * 512 + n];
    float v3 = Wn[3 * FF + k * 512 + n];
    __nv_bfloat16 h, l;
    size_t base = (size_t)n * 2048;
    split1(v0, h, l); g_Bp_hi[base + k] = h;        g_Bp_lo[base + k] = l;
    split1(v1, h, l); g_Bp_hi[base + 512 + k] = h;  g_Bp_lo[base + 512 + k] = l;
    split1(v2, h, l); g_Bp_hi[base + 1024 + k] = h; g_Bp_lo[base + 1024 + k] = l;
    split1(v3, h, l); g_Bp_hi[base + 1536 + k] = h; g_Bp_lo[base + 1536 + k] = l;
    if (i < 512) g_biasP[i] = b[i] + b[1024 + i] + b[1536 + i];
}
__global__ void wprep_d_kernel(const float* __restrict__ Ws, const float* __restrict__ Wn,
                               const float* __restrict__ b) {
    int i = blockIdx.x * blockDim.x + threadIdx.x;
    if (i >= FF) return;
    int n = i & 511, k = i >> 9;
    float v0 = Ws[FF + k * 512 + n];
    float v1 = Wn[FF + k * 512 + n];
    __nv_bfloat16 h, l;
    size_t base = (size_t)n * 1024;
    split1(v0, h, l); g_Bd_hi[base + k] = h;       g_Bd_lo[base + k] = l;
    split1(v1, h, l); g_Bd_hi[base + 512 + k] = h; g_Bd_lo[base + 512 + k] = l;
    if (i < 512) g_biasD[i] = b[512 + i];
}
__global__ void wprep_q_kernel(const float* __restrict__ W, int which) {
    int i = blockIdx.x * blockDim.x + threadIdx.x;
    if (i >= FF) return;
    int n = i & 511, k = i >> 9;
    __nv_bfloat16 h, l;
    split1(W[k * 512 + n], h, l);
    g_Bq_hi[which][n * 512 + k] = h;
    g_Bq_lo[which][n * 512 + k] = l;
}

// ================= tcgen05 bf16-split GEMM =================
// C[M,512](tile 128x128) = Ahi*Bhi + Ahi*Blo + Alo*Bhi (fp32 TMEM accum), + bias
#define GEMM_SMEM (1024 + 4 * 16384)
__global__ __launch_bounds__(128)
void mma_gemm_kernel(const __nv_bfloat16* __restrict__ Ahi, const __nv_bfloat16* __restrict__ Alo,
                     int lda,
                     const __nv_bfloat16* __restrict__ Bhi, const __nv_bfloat16* __restrict__ Blo,
                     int ldb, int Ktot, int M,
                     const float* __restrict__ bias, float* __restrict__ C) {
#if HAS_TCGEN05
    extern __shared__ char smem[];
    uint32_t sb = smem_to_u32(smem);
    const int tid = threadIdx.x;
    const int wid = tid >> 5, lid = tid & 31;
    const int m0 = blockIdx.y * 128, n0 = blockIdx.x * 128;
    const int OAH = 1024, OAL = 1024 + 16384, OBH = 1024 + 32768, OBL = 1024 + 49152;

    if (wid == 0) { TCGEN05_ALLOC(sb, 128); TCGEN05_RELINQ(); }
    if (tid == 0) MBARRIER_INIT(sb + 8, 1);
    __syncthreads();
    uint32_t tbase;
    asm volatile("ld.shared.b32 %0, [%1];" : "=r"(tbase) : "r"(sb));

    const uint64_t dAh = MAKE_SMEM_DESC(sb + OAH);
    const uint64_t dAl = MAKE_SMEM_DESC(sb + OAL);
    const uint64_t dBh = MAKE_SMEM_DESC(sb + OBH);
    const uint64_t dBl = MAKE_SMEM_DESC(sb + OBL);
    const uint32_t idesc = 0x8200490u;   // F32 acc, bf16 A/B, M=128, N=128

    const int nst = Ktot >> 6;   // KC = 64
    for (int s = 0; s < nst; s++) {
        int k0 = s << 6;
        #pragma unroll
        for (int c = 0; c < 8; c++) {
            int chunk = c * 128 + tid;
            int row = chunk >> 3, ch = chunk & 7;
            uint32_t sw = SMEM_SWIZZLE_128B((uint32_t)(row * 128 + ch * 16));
            size_t ga = (size_t)(m0 + row) * lda + k0 + ch * 8;
            size_t gb = (size_t)(n0 + row) * ldb + k0 + ch * 8;
            *(uint4*)(smem + OAH + sw) = *(const uint4*)(Ahi + ga);
            *(uint4*)(smem + OAL + sw) = *(const uint4*)(Alo + ga);
            *(uint4*)(smem + OBH + sw) = *(const uint4*)(Bhi + gb);
            *(uint4*)(smem + OBL + sw) = *(const uint4*)(Blo + gb);
        }
        FENCE_ASYNC_SHARED();
        __syncthreads();
        if (wid == 0 && elect_one_pred()) {
            #pragma unroll
            for (int kk = 0; kk < 4; kk++) {
                uint64_t o = (uint64_t)(kk * 2);
                mma_bf16_ss(tbase, dAh + o, dBh + o, idesc, !(s == 0 && kk == 0));
                mma_bf16_ss(tbase, dAh + o, dBl + o, idesc, 1u);
                mma_bf16_ss(tbase, dAl + o, dBh + o, idesc, 1u);
            }
            TCGEN05_COMMIT(sb + 8);
        }
        MBARRIER_WAIT_PARITY(sb + 8, s & 1);
    }
    TCGEN05_FENCE_AFTER();

    int gr = m0 + wid * 32 + lid;
    #pragma unroll
    for (int base = 0; base < 128; base += 32) {
        uint32_t r[32];
        TCGEN05_LD_X32(r, tbase + base);
        TCGEN05_WAIT_LD();
        if (gr < M) {
            float* cp = C + (size_t)gr * 512 + n0 + base;
            #pragma unroll
            for (int j = 0; j < 32; j += 4) {
                float4 v;
                v.x = __uint_as_float(r[j + 0]) + bias[n0 + base + j + 0];
                v.y = __uint_as_float(r[j + 1]) + bias[n0 + base + j + 1];
                v.z = __uint_as_float(r[j + 2]) + bias[n0 + base + j + 2];
                v.w = __uint_as_float(r[j + 3]) + bias[n0 + base + j + 3];
                *(float4*)(cp + j) = v;
            }
        }
    }
    TCGEN05_FENCE_BEFORE();
    __syncthreads();
    if (tid == 0) MBARRIER_INVAL(sb + 8);
    __syncthreads();
    if (wid == 0) TCGEN05_DEALLOC(tbase, 128);
#else
    // Correct scalar fallback (only ever used if a non-sm_103a binary is run).
    // Same math: hi*hi + hi*lo + lo*hi in fp32.
    const int tid = threadIdx.x;
    const int m0 = blockIdx.y * 128, n0 = blockIdx.x * 128;
    for (int rc = tid; rc < 128 * 128; rc += blockDim.x) {
        int r = rc >> 7, c = rc & 127;
        int gr = m0 + r, gc = n0 + c;
        if (gr >= M) continue;
        const __nv_bfloat16* ah = Ahi + (size_t)gr * lda;
        const __nv_bfloat16* al = Alo + (size_t)gr * lda;
        const __nv_bfloat16* bh = Bhi + (size_t)gc * ldb;
        const __nv_bfloat16* bl = Blo + (size_t)gc * ldb;
        float acc = 0.f;
        for (int k = 0; k < Ktot; k++) {
            float ahv = __bfloat162float(ah[k]), alv = __bfloat162float(al[k]);
            float bhv = __bfloat162float(bh[k]), blv = __bfloat162float(bl[k]);
            acc += ahv * bhv + ahv * blv + alv * bhv;
        }
        C[(size_t)gr * 512 + gc] = acc + bias[gc];
    }
#endif
}

// ================= BatchNorm + ReLU =================
__global__ void zero_stats_kernel() {
    int i = threadIdx.x;
    if (i < 2 * FEAT) g_bnstat[i] = 0.f;
}
__global__ void bn_reduce_kernel(const float* __restrict__ x) {
    int col = blockIdx.x * 256 + threadIdx.x;   // grid.x = 2
    float s = 0.f, s2 = 0.f;
    for (int r = blockIdx.y; r < NNODE; r += gridDim.y) {
        float v = x[(size_t)r * FEAT + col];
        s += v; s2 += v * v;
    }
    atomicAdd(&g_bnstat[col], s);
    atomicAdd(&g_bnstat[FEAT + col], s2);
}
__global__ void bn_norm_split_kernel(const float* __restrict__ raw, float* __restrict__ f32out,
                                     __nv_bfloat16* __restrict__ hi, __nv_bfloat16* __restrict__ lo,
                                     int lda,
                                     const float* __restrict__ gamma, const float* __restrict__ beta) {
    size_t idx = (size_t)blockIdx.x * blockDim.x + threadIdx.x;
    if (idx >= (size_t)NNODE * FEAT) return;
    int col = (int)(idx & (FEAT - 1));
    int row = (int)(idx >> 9);
    float mean = g_bnstat[col] * (1.0f / NNODE);
    float var  = g_bnstat[FEAT + col] * (1.0f / NNODE) - mean * mean;
    float sc = gamma[col] * rsqrtf(var + BN_EPS);
    float v = (raw[idx] - mean) * sc + beta[col];
    v = v > 0.f ? v : 0.f;
    f32out[idx] = v;
    __nv_bfloat16 h, l;
    split1(v, h, l);
    size_t o = (size_t)row * lda + col;
    hi[o] = h; lo[o] = l;
}

// ================= host orchestration =================
extern "C" void kernel_launch(void* const* d_in, const int* in_sizes, int n_in,
                              void* d_out, int out_size) {
    const float* h_d  = (const float*)d_in[0];
    const float* h_p  = (const float*)d_in[1];
    const float* Ws1  = (const float*)d_in[2];
    const float* Wn1  = (const float*)d_in[3];
    const float* b1   = (const float*)d_in[4];
    const float* Ws2  = (const float*)d_in[5];
    const float* Wn2  = (const float*)d_in[6];
    const float* b2   = (const float*)d_in[7];
    const float* gam  = (const float*)d_in[8];
    const float* bet  = (const float*)d_in[9];
    const float* pWd  = (const float*)d_in[10];
    const float* pbd  = (const float*)d_in[11];
    const float* pWp  = (const float*)d_in[12];
    const float* pbp  = (const float*)d_in[13];
    const int* a_src = (const int*)d_in[14];
    const int* a_dst = (const int*)d_in[15];
    const int* i_src = (const int*)d_in[16];
    const int* i_dst = (const int*)d_in[17];
    int E = in_sizes[14];

    float* out_d = (float*)d_out;
    float* out_p = out_d + (size_t)NNODE * FEAT;

    __nv_bfloat16 *ApH, *ApL, *AdH, *AdL, *BpH, *BpL, *BdH, *BdL, *BqH, *BqL;
    float *rawd, *rawp, *hdf, *hpf, *biasP, *biasD;
    cudaGetSymbolAddress((void**)&ApH, g_Ap_hi);
    cudaGetSymbolAddress((void**)&ApL, g_Ap_lo);
    cudaGetSymbolAddress((void**)&AdH, g_Ad_hi);
    cudaGetSymbolAddress((void**)&AdL, g_Ad_lo);
    cudaGetSymbolAddress((void**)&BpH, g_Bp_hi);
    cudaGetSymbolAddress((void**)&BpL, g_Bp_lo);
    cudaGetSymbolAddress((void**)&BdH, g_Bd_hi);
    cudaGetSymbolAddress((void**)&BdL, g_Bd_lo);
    cudaGetSymbolAddress((void**)&BqH, g_Bq_hi);
    cudaGetSymbolAddress((void**)&BqL, g_Bq_lo);
    cudaGetSymbolAddress((void**)&rawd, g_rawd);
    cudaGetSymbolAddress((void**)&rawp, g_rawp);
    cudaGetSymbolAddress((void**)&hdf, g_hdf);
    cudaGetSymbolAddress((void**)&hpf, g_hpf);
    cudaGetSymbolAddress((void**)&biasP, g_biasP);
    cudaGetSymbolAddress((void**)&biasD, g_biasD);

    cudaFuncSetAttribute(mma_gemm_kernel, cudaFuncAttributeMaxDynamicSharedMemorySize, GEMM_SMEM);

    const int NW = (NNODE * FEAT + 255) / 256;
    const dim3 gg(4, (NNODE + 127) / 128);

    // ---- CSR build ----
    zero_cnt_kernel<<<(4 * NNODE + 255) / 256, 256>>>();
    hist_kernel<<<(4 * E + 255) / 256, 256>>>(a_src, a_dst, i_src, i_dst, E);
    scan_kernel<<<4, 1024>>>();
    fill_kernel<<<(4 * E + 255) / 256, 256>>>(a_src, a_dst, i_src, i_dst, E);

    // ---- layer 1 ----
    wprep_p_kernel<<<(FF + 255) / 256, 256>>>(Ws1, Wn1, b1);
    wprep_d_kernel<<<(FF + 255) / 256, 256>>>(Ws1, Wn1, b1);
    split_input_kernel<<<NW, 256>>>(h_p, ApH, ApL, 2048, 0);
    split_input_kernel<<<NW, 256>>>(h_d, AdH, AdL, 1024, 0);
    gather_split_kernel<<<NNODE, 128>>>(h_d, 0, E, ApH, ApL, 2048, 512);
    gather_split_kernel<<<NNODE, 128>>>(h_p, 2, E, ApH, ApL, 2048, 1024);
    gather_split_kernel<<<NNODE, 128>>>(h_p, 3, E, ApH, ApL, 2048, 1536);
    gather_split_kernel<<<NNODE, 128>>>(h_p, 1, E, AdH, AdL, 1024, 512);
    mma_gemm_kernel<<<gg, 128, GEMM_SMEM>>>(ApH, ApL, 2048, BpH, BpL, 2048, 2048, NNODE, biasP, rawp);
    mma_gemm_kernel<<<gg, 128, GEMM_SMEM>>>(AdH, AdL, 1024, BdH, BdL, 1024, 1024, NNODE, biasD, rawd);
    zero_stats_kernel<<<1, 1024>>>();
    bn_reduce_kernel<<<dim3(2, 64), 256>>>(rawd);
    bn_norm_split_kernel<<<NW, 256>>>(rawd, hdf, AdH, AdL, 1024, gam + 0 * FEAT, bet + 0 * FEAT);
    zero_stats_kernel<<<1, 1024>>>();
    bn_reduce_kernel<<<dim3(2, 64), 256>>>(rawp);
    bn_norm_split_kernel<<<NW, 256>>>(rawp, hpf, ApH, ApL, 2048, gam + 1 * FEAT, bet + 1 * FEAT);

    // ---- layer 2 ----
    wprep_p_kernel<<<(FF + 255) / 256, 256>>>(Ws2, Wn2, b2);
    wprep_d_kernel<<<(FF + 255) / 256, 256>>>(Ws2, Wn2, b2);
    gather_split_kernel<<<NNODE, 128>>>(hdf, 0, E, ApH, ApL, 2048, 512);
    gather_split_kernel<<<NNODE, 128>>>(hpf, 2, E, ApH, ApL, 2048, 1024);
    gather_split_kernel<<<NNODE, 128>>>(hpf, 3, E, ApH, ApL, 2048, 1536);
    gather_split_kernel<<<NNODE, 128>>>(hpf, 1, E, AdH, AdL, 1024, 512);
    mma_gemm_kernel<<<gg, 128, GEMM_SMEM>>>(ApH, ApL, 2048, BpH, BpL, 2048, 2048, NNODE, biasP, rawp);
    mma_gemm_kernel<<<gg, 128, GEMM_SMEM>>>(AdH, AdL, 1024, BdH, BdL, 1024, 1024, NNODE, biasD, rawd);
    zero_stats_kernel<<<1, 1024>>>();
    bn_reduce_kernel<<<dim3(2, 64), 256>>>(rawd);
    bn_norm_split_kernel<<<NW, 256>>>(rawd, hdf, AdH, AdL, 1024, gam + 2 * FEAT, bet + 2 * FEAT);
    zero_stats_kernel<<<1, 1024>>>();
    bn_reduce_kernel<<<dim3(2, 64), 256>>>(rawp);
    bn_norm_split_kernel<<<NW, 256>>>(rawp, hpf, ApH, ApL, 2048, gam + 3 * FEAT, bet + 3 * FEAT);

    // ---- projections ----
    wprep_q_kernel<<<(FF + 255) / 256, 256>>>(pWd, 0);
    wprep_q_kernel<<<(FF + 255) / 256, 256>>>(pWp, 1);
    mma_gemm_kernel<<<gg, 128, GEMM_SMEM>>>(AdH, AdL, 1024, BqH, BqL, 512, 512, NNODE, pbd, out_d);
    mma_gemm_kernel<<<gg, 128, GEMM_SMEM>>>(ApH, ApL, 2048, BqH + FF, BqL + FF, 512, 512, NNODE, pbp, out_p);
}

// round 4
// speedup vs baseline: 3.3962x; 1.7466x over previous
#include <cuda_runtime.h>
#include <cuda_bf16.h>
#include <cstdint>

#define NNODE 20000
#define MPAD  20096
#define FEAT  512
#define EMAX  320000
#define FF    (FEAT*FEAT)
#define BN_EPS 1e-5f

#if defined(__CUDA_ARCH_FEAT_SM103_ALL) || defined(__CUDA_ARCH_FEAT_SM100_ALL) || defined(__CUDA_ARCH_FEAT_SM101_ALL)
#define HAS_TCGEN05 1
#else
#define HAS_TCGEN05 0
#endif

// ================= device scratch (static, no allocs) =================
__device__ __nv_bfloat16 g_Ap_hi[(size_t)MPAD * 2048];
__device__ __nv_bfloat16 g_Ap_lo[(size_t)MPAD * 2048];
__device__ __nv_bfloat16 g_Ad_hi[(size_t)MPAD * 1024];
__device__ __nv_bfloat16 g_Ad_lo[(size_t)MPAD * 1024];
__device__ __nv_bfloat16 g_Bp_hi[512 * 2048];
__device__ __nv_bfloat16 g_Bp_lo[512 * 2048];
__device__ __nv_bfloat16 g_Bd_hi[512 * 1024];
__device__ __nv_bfloat16 g_Bd_lo[512 * 1024];
__device__ __nv_bfloat16 g_Bq_hi[2][512 * 512];
__device__ __nv_bfloat16 g_Bq_lo[2][512 * 512];
__device__ float g_biasP[FEAT];
__device__ float g_biasD[FEAT];
__device__ float g_rawd[(size_t)NNODE * FEAT];
__device__ float g_rawp[(size_t)NNODE * FEAT];
__device__ float g_hdf [(size_t)NNODE * FEAT];
__device__ float g_hpf [(size_t)NNODE * FEAT];
__device__ float g_bnstat[2 * FEAT];
__device__ int   g_cnt[4 * NNODE];
__device__ int   g_cur[4 * NNODE];
__device__ int   g_off[4 * (NNODE + 1)];
__device__ int   g_adj[4 * EMAX];

// ================= PTX helpers =================
__device__ __forceinline__ uint32_t smem_to_u32(const void* p) {
    uint32_t a;
    asm("{ .reg .u64 t; cvta.to.shared.u64 t, %1; cvt.u32.u64 %0, t; }" : "=r"(a) : "l"(p));
    return a;
}
__device__ __forceinline__ uint32_t elect_one_pred() {
    uint32_t pred;
    asm volatile("{\n\t.reg .pred p;\n\telect.sync _|p, 0xFFFFFFFF;\n\tselp.b32 %0, 1, 0, p;\n\t}" : "=r"(pred));
    return pred;
}
#define SMEM_SWIZZLE_128B(o) ((o) ^ (((o) >> 3) & 0x70))
static constexpr uint64_t SMEM_DESC_BASE_SW128 =
    (uint64_t(2) << 61) | (uint64_t(1) << 46) | (uint64_t(64) << 32) | (uint64_t(1) << 16);
#define MAKE_SMEM_DESC(base) (SMEM_DESC_BASE_SW128 | ((uint64_t)((base) >> 4) & 0x3FFF))

// cp.async (sm_80+, valid in all compilation passes)
#define CP_ASYNC16(dst, src) \
    asm volatile("cp.async.cg.shared.global [%0], [%1], 16;" :: "r"(dst), "l"(src) : "memory")
#define CP_COMMIT() asm volatile("cp.async.commit_group;" ::: "memory")
#define CP_WAIT1() asm volatile("cp.async.wait_group 1;" ::: "memory")
#define CP_WAIT0() asm volatile("cp.async.wait_group 0;" ::: "memory")

#if HAS_TCGEN05
#define TCGEN05_ALLOC(sm, n) \
    asm volatile("tcgen05.alloc.cta_group::1.sync.aligned.shared::cta.b32 [%0], %1;" \
                 :: "r"((uint32_t)(sm)), "r"((uint32_t)(n)) : "memory")
#define TCGEN05_DEALLOC(t, n) \
    asm volatile("tcgen05.dealloc.cta_group::1.sync.aligned.b32 %0, %1;" :: "r"(t), "r"((uint32_t)(n)))
#define TCGEN05_RELINQ() \
    asm volatile("tcgen05.relinquish_alloc_permit.cta_group::1.sync.aligned;")
#define TCGEN05_COMMIT(mb) \
    asm volatile("tcgen05.commit.cta_group::1.mbarrier::arrive::one.shared::cluster.b64 [%0];" \
                 :: "r"((uint32_t)(mb)) : "memory")
#define TCGEN05_WAIT_LD()  asm volatile("tcgen05.wait::ld.sync.aligned;" ::: "memory")
#define TCGEN05_FENCE_BEFORE() asm volatile("tcgen05.fence::before_thread_sync;" ::: "memory")
#define TCGEN05_FENCE_AFTER()  asm volatile("tcgen05.fence::after_thread_sync;" ::: "memory")
#define FENCE_ASYNC_SHARED() asm volatile("fence.proxy.async.shared::cta;" ::: "memory")
#define MBARRIER_INIT(mb, c) \
    asm volatile("mbarrier.init.shared.b64 [%0], %1;" :: "r"((uint32_t)(mb)), "r"((uint32_t)(c)) : "memory")
#define MBARRIER_INVAL(mb) \
    asm volatile("mbarrier.inval.shared.b64 [%0];" :: "r"((uint32_t)(mb)) : "memory")
#define MBARRIER_WAIT_PARITY(mb, ph) do { \
    uint32_t _mb = (uint32_t)(mb), _ph = (uint32_t)(ph), _done; \
    asm volatile("{\n\t.reg .pred p;\n\tmbarrier.try_wait.parity.acquire.cta.shared::cta.b64 p, [%1], %2;\n\tselp.b32 %0, 1, 0, p;\n\t}" \
        : "=r"(_done) : "r"(_mb), "r"(_ph) : "memory"); \
    if (!_done) { \
        asm volatile("{\n\t.reg .pred P1;\n\tWL_%=: \n\tmbarrier.try_wait.parity.acquire.cta.shared::cta.b64 P1, [%0], %1, 0x989680;\n\t@P1 bra.uni WD_%=;\n\tbra.uni WL_%=;\n\tWD_%=: \n\t}" \
            :: "r"(_mb), "r"(_ph) : "memory"); \
    } \
} while (0)

#define TCGEN05_LD_X32(r, addr) \
    asm volatile("tcgen05.ld.sync.aligned.32x32b.x32.b32 " \
        "{%0, %1, %2, %3, %4, %5, %6, %7, %8, %9, %10, %11, %12, %13, %14, %15, " \
        " %16, %17, %18, %19, %20, %21, %22, %23, %24, %25, %26, %27, %28, %29, %30, %31}, [%32];" \
        : "=r"((r)[0]), "=r"((r)[1]), "=r"((r)[2]), "=r"((r)[3]), "=r"((r)[4]), "=r"((r)[5]), "=r"((r)[6]), "=r"((r)[7]), \
          "=r"((r)[8]), "=r"((r)[9]), "=r"((r)[10]), "=r"((r)[11]), "=r"((r)[12]), "=r"((r)[13]), "=r"((r)[14]), "=r"((r)[15]), \
          "=r"((r)[16]), "=r"((r)[17]), "=r"((r)[18]), "=r"((r)[19]), "=r"((r)[20]), "=r"((r)[21]), "=r"((r)[22]), "=r"((r)[23]), \
          "=r"((r)[24]), "=r"((r)[25]), "=r"((r)[26]), "=r"((r)[27]), "=r"((r)[28]), "=r"((r)[29]), "=r"((r)[30]), "=r"((r)[31]) \
        : "r"(addr))

__device__ __forceinline__ void mma_bf16_ss(uint32_t d_tmem, uint64_t a_desc, uint64_t b_desc,
                                            uint32_t idesc, uint32_t enable) {
    asm volatile(
        "{\n\t.reg .pred p;\n\tsetp.ne.u32 p, %5, 0;\n\t"
        "tcgen05.mma.cta_group::1.kind::f16 [%0], %1, %2, %3, {%4, %4, %4, %4}, p;\n\t}"
        :: "r"(d_tmem), "l"(a_desc), "l"(b_desc), "r"(idesc), "r"(0u), "r"(enable)
        : "memory");
}
#endif // HAS_TCGEN05

__device__ __forceinline__ void split1(float v, __nv_bfloat16& h, __nv_bfloat16& l) {
    h = __float2bfloat16(v);
    l = __float2bfloat16(v - __bfloat162float(h));
}

// ================= CSR build =================
__global__ void zero_cnt_kernel() {
    int i = blockIdx.x * blockDim.x + threadIdx.x;
    if (i < 4 * NNODE) g_cnt[i] = 0;
}
__global__ void hist_kernel(const int* __restrict__ a_src, const int* __restrict__ a_dst,
                            const int* __restrict__ i_src, const int* __restrict__ i_dst, int E) {
    int i = blockIdx.x * blockDim.x + threadIdx.x;
    if (i >= 4 * E) return;
    int w = i / E, e = i - w * E;
    int k = (w == 0) ? a_dst[e] : (w == 1) ? a_src[e] : (w == 2) ? i_dst[e] : i_src[e];
    atomicAdd(&g_cnt[w * NNODE + k], 1);
}
__global__ void scan_kernel() {
    int c = blockIdx.x;
    __shared__ int sh[1024];
    __shared__ int carry_sh;
    int tid = threadIdx.x;
    if (tid == 0) { carry_sh = 0; g_off[c * (NNODE + 1)] = 0; }
    __syncthreads();
    for (int base = 0; base < NNODE; base += 1024) {
        int i = base + tid;
        int v = (i < NNODE) ? g_cnt[c * NNODE + i] : 0;
        sh[tid] = v;
        __syncthreads();
        #pragma unroll
        for (int d = 1; d < 1024; d <<= 1) {
            int t = (tid >= d) ? sh[tid - d] : 0;
            __syncthreads();
            sh[tid] += t;
            __syncthreads();
        }
        int incl = sh[tid];
        int carry = carry_sh;
        __syncthreads();
        if (i < NNODE) {
            g_off[c * (NNODE + 1) + i + 1] = carry + incl;
            g_cur[c * NNODE + i] = carry + incl - v;
        }
        if (tid == 1023) carry_sh = carry + sh[1023];
        __syncthreads();
    }
}
__global__ void fill_kernel(const int* __restrict__ a_src, const int* __restrict__ a_dst,
                            const int* __restrict__ i_src, const int* __restrict__ i_dst, int E) {
    int i = blockIdx.x * blockDim.x + threadIdx.x;
    if (i >= 4 * E) return;
    int w = i / E, e = i - w * E;
    int k = (w == 0) ? a_dst[e] : (w == 1) ? a_src[e] : (w == 2) ? i_dst[e] : i_src[e];
    int v = (w == 0) ? a_src[e] : (w == 1) ? a_dst[e] : (w == 2) ? i_src[e] : i_dst[e];
    int pos = atomicAdd(&g_cur[w * NNODE + k], 1);
    g_adj[w * E + pos] = v;
}

// ========== fused 4-way segment-mean gather → bf16 hi/lo splits into stacked A slots ==========
__global__ void gather4_kernel(const float* __restrict__ srcD, const float* __restrict__ srcP,
                               __nv_bfloat16* __restrict__ ApH, __nv_bfloat16* __restrict__ ApL,
                               __nv_bfloat16* __restrict__ AdH, __nv_bfloat16* __restrict__ AdL,
                               int E) {
    int c = blockIdx.y;
    const float* src = (c == 0) ? srcD : srcP;
    __nv_bfloat16* hi;
    __nv_bfloat16* lo;
    int lda, coff;
    if (c == 1) { hi = AdH; lo = AdL; lda = 1024; coff = 512; }
    else {
        hi = ApH; lo = ApL; lda = 2048;
        coff = (c == 0) ? 512 : (c == 2) ? 1024 : 1536;
    }
    int n = blockIdx.x;
    int t = threadIdx.x;
    int s = g_off[c * (NNODE + 1) + n];
    int e = g_off[c * (NNODE + 1) + n + 1];
    const int* adj = g_adj + (size_t)c * E;
    float4 acc = make_float4(0.f, 0.f, 0.f, 0.f);
    int j = s;
    for (; j + 1 < e; j += 2) {
        int r0 = adj[j], r1 = adj[j + 1];
        float4 v0 = *(const float4*)(src + (size_t)r0 * FEAT + t * 4);
        float4 v1 = *(const float4*)(src + (size_t)r1 * FEAT + t * 4);
        acc.x += v0.x + v1.x; acc.y += v0.y + v1.y;
        acc.z += v0.z + v1.z; acc.w += v0.w + v1.w;
    }
    if (j < e) {
        int r0 = adj[j];
        float4 v0 = *(const float4*)(src + (size_t)r0 * FEAT + t * 4);
        acc.x += v0.x; acc.y += v0.y; acc.z += v0.z; acc.w += v0.w;
    }
    float inv = (e > s) ? 1.0f / (float)(e - s) : 0.0f;
    float v[4] = {acc.x * inv, acc.y * inv, acc.z * inv, acc.w * inv};
    size_t o = (size_t)n * lda + coff + t * 4;
    __nv_bfloat16 h[4], l[4];
    #pragma unroll
    for (int q = 0; q < 4; q++) split1(v[q], h[q], l[q]);
    *(__nv_bfloat162*)(hi + o)     = *(__nv_bfloat162*)&h[0];
    *(__nv_bfloat162*)(hi + o + 2) = *(__nv_bfloat162*)&h[2];
    *(__nv_bfloat162*)(lo + o)     = *(__nv_bfloat162*)&l[0];
    *(__nv_bfloat162*)(lo + o + 2) = *(__nv_bfloat162*)&l[2];
}

// ========== split fp32 matrix into stacked-A slot ==========
__global__ void split_input_kernel(const float* __restrict__ src,
                                   __nv_bfloat16* __restrict__ hi, __nv_bfloat16* __restrict__ lo,
                                   int lda, int coff) {
    size_t idx = (size_t)blockIdx.x * blockDim.x + threadIdx.x;
    if (idx >= (size_t)NNODE * FEAT) return;
    int row = (int)(idx >> 9), col = (int)(idx & 511);
    float v = src[idx];
    __nv_bfloat16 h, l;
    split1(v, h, l);
    size_t o = (size_t)row * lda + coff + col;
    hi[o] = h; lo[o] = l;
}

// ========== weight prep: transpose + fuse + split ==========
__global__ void wprep_p_kernel(const float* __restrict__ Ws, const float* __restrict__ Wn,
                               const float* __restrict__ b) {
    int i = blockIdx.x * blockDim.x + threadIdx.x;
    if (i >= FF) return;
    int n = i & 511, k = i >> 9;
    float v0 = Ws[k * 512 + n] + Ws[2 * FF + k * 512 + n] + Ws[3 * FF + k * 512 + n];
    float v1 = Wn[0 * FF + k * 512 + n];
    float v2 = Wn[2 * FF + k * 512 + n];
    float v3 = Wn[3 * FF + k * 512 + n];
    __nv_bfloat16 h, l;
    size_t base = (size_t)n * 2048;
    split1(v0, h, l); g_Bp_hi[base + k] = h;        g_Bp_lo[base + k] = l;
    split1(v1, h, l); g_Bp_hi[base + 512 + k] = h;  g_Bp_lo[base + 512 + k] = l;
    split1(v2, h, l); g_Bp_hi[base + 1024 + k] = h; g_Bp_lo[base + 1024 + k] = l;
    split1(v3, h, l); g_Bp_hi[base + 1536 + k] = h; g_Bp_lo[base + 1536 + k] = l;
    if (i < 512) g_biasP[i] = b[i] + b[1024 + i] + b[1536 + i];
}
__global__ void wprep_d_kernel(const float* __restrict__ Ws, const float* __restrict__ Wn,
                               const float* __restrict__ b) {
    int i = blockIdx.x * blockDim.x + threadIdx.x;
    if (i >= FF) return;
    int n = i & 511, k = i >> 9;
    float v0 = Ws[FF + k * 512 + n];
    float v1 = Wn[FF + k * 512 + n];
    __nv_bfloat16 h, l;
    size_t base = (size_t)n * 1024;
    split1(v0, h, l); g_Bd_hi[base + k] = h;       g_Bd_lo[base + k] = l;
    split1(v1, h, l); g_Bd_hi[base + 512 + k] = h; g_Bd_lo[base + 512 + k] = l;
    if (i < 512) g_biasD[i] = b[512 + i];
}
__global__ void wprep_q_kernel(const float* __restrict__ W, int which) {
    int i = blockIdx.x * blockDim.x + threadIdx.x;
    if (i >= FF) return;
    int n = i & 511, k = i >> 9;
    __nv_bfloat16 h, l;
    split1(W[k * 512 + n], h, l);
    g_Bq_hi[which][n * 512 + k] = h;
    g_Bq_lo[which][n * 512 + k] = l;
}

// ================= pipelined tcgen05 bf16-split GEMM, 128x256 tile =================
// C[128,256] = Ahi*Bhi + Ahi*Blo + Alo*Bhi (fp32 TMEM accum) + bias
// cp.async double-buffered: loads of stage s+1 overlap MMA of stage s.
#define STAGE_BYTES (16384 + 16384 + 32768 + 32768)   // AH AL BH BL = 96KB
#define GEMM_SMEM (1024 + 2 * STAGE_BYTES)
__global__ __launch_bounds__(128)
void mma_gemm_kernel(const __nv_bfloat16* __restrict__ Ahi, const __nv_bfloat16* __restrict__ Alo,
                     int lda,
                     const __nv_bfloat16* __restrict__ Bhi, const __nv_bfloat16* __restrict__ Blo,
                     int ldb, int Ktot, int M,
                     const float* __restrict__ bias, float* __restrict__ C) {
#if HAS_TCGEN05
    extern __shared__ char smem[];
    uint32_t sb = smem_to_u32(smem);
    const int tid = threadIdx.x;
    const int wid = tid >> 5, lid = tid & 31;
    const int m0 = blockIdx.y * 128, n0 = blockIdx.x * 256;

    if (wid == 0) { TCGEN05_ALLOC(sb, 256); TCGEN05_RELINQ(); }
    if (tid == 0) MBARRIER_INIT(sb + 8, 1);
    __syncthreads();
    uint32_t tbase;
    asm volatile("ld.shared.b32 %0, [%1];" : "=r"(tbase) : "r"(sb));

    const uint32_t idesc = 0x8400490u;   // F32 acc, bf16 A/B, M=128, N=256
    const int nst = Ktot >> 6;           // KC = 64

    // per-thread static load addressing: A tiles 128 rows x 8 chunks, B tiles 256 rows x 8 chunks
    const int arow = tid >> 1;           // reused pattern below via loops

    auto issue_loads = [&](int s) {
        int k0 = s << 6;
        uint32_t base = sb + 1024 + (uint32_t)(s & 1) * STAGE_BYTES;
        // A hi/lo: 1024 chunks each
        #pragma unroll
        for (int c = 0; c < 8; c++) {
            int chunk = c * 128 + tid;
            int row = chunk >> 3, ch = chunk & 7;
            uint32_t sw = SMEM_SWIZZLE_128B((uint32_t)(row * 128 + ch * 16));
            size_t ga = (size_t)(m0 + row) * lda + k0 + ch * 8;
            CP_ASYNC16(base + sw, Ahi + ga);
            CP_ASYNC16(base + 16384 + sw, Alo + ga);
        }
        // B hi/lo: 2048 chunks each
        #pragma unroll
        for (int c = 0; c < 16; c++) {
            int chunk = c * 128 + tid;
            int row = chunk >> 3, ch = chunk & 7;
            uint32_t sw = SMEM_SWIZZLE_128B((uint32_t)(row * 128 + ch * 16));
            size_t gb = (size_t)(n0 + row) * ldb + k0 + ch * 8;
            CP_ASYNC16(base + 32768 + sw, Bhi + gb);
            CP_ASYNC16(base + 65536 + sw, Blo + gb);
        }
        CP_COMMIT();
    };

    issue_loads(0);
    for (int s = 0; s < nst; s++) {
        if (s >= 1) MBARRIER_WAIT_PARITY(sb + 8, (s - 1) & 1);  // MMA s-1 done -> buf (s+1)&1 free
        if (s + 1 < nst) { issue_loads(s + 1); CP_WAIT1(); }
        else             { CP_WAIT0(); }
        __syncthreads();
        FENCE_ASYNC_SHARED();
        if (wid == 0 && elect_one_pred()) {
            uint32_t bufb = sb + 1024 + (uint32_t)(s & 1) * STAGE_BYTES;
            uint64_t dAh = MAKE_SMEM_DESC(bufb);
            uint64_t dAl = MAKE_SMEM_DESC(bufb + 16384);
            uint64_t dBh = MAKE_SMEM_DESC(bufb + 32768);
            uint64_t dBl = MAKE_SMEM_DESC(bufb + 65536);
            #pragma unroll
            for (int kk = 0; kk < 4; kk++) {
                uint64_t o = (uint64_t)(kk * 2);
                mma_bf16_ss(tbase, dAh + o, dBh + o, idesc, !(s == 0 && kk == 0));
                mma_bf16_ss(tbase, dAh + o, dBl + o, idesc, 1u);
                mma_bf16_ss(tbase, dAl + o, dBh + o, idesc, 1u);
            }
            TCGEN05_COMMIT(sb + 8);
        }
    }
    MBARRIER_WAIT_PARITY(sb + 8, (nst - 1) & 1);
    TCGEN05_FENCE_AFTER();

    int gr = m0 + wid * 32 + lid;
    #pragma unroll
    for (int base = 0; base < 256; base += 32) {
        uint32_t r[32];
        TCGEN05_LD_X32(r, tbase + base);
        TCGEN05_WAIT_LD();
        if (gr < M) {
            float* cp = C + (size_t)gr * 512 + n0 + base;
            #pragma unroll
            for (int j = 0; j < 32; j += 4) {
                float4 v;
                v.x = __uint_as_float(r[j + 0]) + bias[n0 + base + j + 0];
                v.y = __uint_as_float(r[j + 1]) + bias[n0 + base + j + 1];
                v.z = __uint_as_float(r[j + 2]) + bias[n0 + base + j + 2];
                v.w = __uint_as_float(r[j + 3]) + bias[n0 + base + j + 3];
                *(float4*)(cp + j) = v;
            }
        }
    }
    TCGEN05_FENCE_BEFORE();
    __syncthreads();
    if (tid == 0) MBARRIER_INVAL(sb + 8);
    __syncthreads();
    if (wid == 0) TCGEN05_DEALLOC(tbase, 256);
#else
    // Correct scalar fallback (only used if a non-sm_103a binary were run).
    const int tid = threadIdx.x;
    const int m0 = blockIdx.y * 128, n0 = blockIdx.x * 256;
    for (int rc = tid; rc < 128 * 256; rc += blockDim.x) {
        int r = rc >> 8, c = rc & 255;
        int gr = m0 + r, gc = n0 + c;
        if (gr >= M) continue;
        const __nv_bfloat16* ah = Ahi + (size_t)gr * lda;
        const __nv_bfloat16* al = Alo + (size_t)gr * lda;
        const __nv_bfloat16* bh = Bhi + (size_t)gc * ldb;
        const __nv_bfloat16* bl = Blo + (size_t)gc * ldb;
        float acc = 0.f;
        for (int k = 0; k < Ktot; k++) {
            float ahv = __bfloat162float(ah[k]), alv = __bfloat162float(al[k]);
            float bhv = __bfloat162float(bh[k]), blv = __bfloat162float(bl[k]);
            acc += ahv * bhv + ahv * blv + alv * bhv;
        }
        C[(size_t)gr * 512 + gc] = acc + bias[gc];
    }
#endif
}

// ================= BatchNorm + ReLU =================
__global__ void zero_stats_kernel() {
    int i = threadIdx.x;
    if (i < 2 * FEAT) g_bnstat[i] = 0.f;
}
__global__ void bn_reduce_kernel(const float* __restrict__ x) {
    int col = blockIdx.x * 256 + threadIdx.x;   // grid.x = 2
    float s = 0.f, s2 = 0.f;
    for (int r = blockIdx.y; r < NNODE; r += gridDim.y) {
        float v = x[(size_t)r * FEAT + col];
        s += v; s2 += v * v;
    }
    atomicAdd(&g_bnstat[col], s);
    atomicAdd(&g_bnstat[FEAT + col], s2);
}
__global__ void bn_norm_split_kernel(const float* __restrict__ raw, float* __restrict__ f32out,
                                     __nv_bfloat16* __restrict__ hi, __nv_bfloat16* __restrict__ lo,
                                     int lda,
                                     const float* __restrict__ gamma, const float* __restrict__ beta) {
    size_t idx = (size_t)blockIdx.x * blockDim.x + threadIdx.x;
    if (idx >= (size_t)NNODE * FEAT) return;
    int col = (int)(idx & (FEAT - 1));
    int row = (int)(idx >> 9);
    float mean = g_bnstat[col] * (1.0f / NNODE);
    float var  = g_bnstat[FEAT + col] * (1.0f / NNODE) - mean * mean;
    float sc = gamma[col] * rsqrtf(var + BN_EPS);
    float v = (raw[idx] - mean) * sc + beta[col];
    v = v > 0.f ? v : 0.f;
    f32out[idx] = v;
    __nv_bfloat16 h, l;
    split1(v, h, l);
    size_t o = (size_t)row * lda + col;
    hi[o] = h; lo[o] = l;
}

// ================= host orchestration =================
extern "C" void kernel_launch(void* const* d_in, const int* in_sizes, int n_in,
                              void* d_out, int out_size) {
    const float* h_d  = (const float*)d_in[0];
    const float* h_p  = (const float*)d_in[1];
    const float* Ws1  = (const float*)d_in[2];
    const float* Wn1  = (const float*)d_in[3];
    const float* b1   = (const float*)d_in[4];
    const float* Ws2  = (const float*)d_in[5];
    const float* Wn2  = (const float*)d_in[6];
    const float* b2   = (const float*)d_in[7];
    const float* gam  = (const float*)d_in[8];
    const float* bet  = (const float*)d_in[9];
    const float* pWd  = (const float*)d_in[10];
    const float* pbd  = (const float*)d_in[11];
    const float* pWp  = (const float*)d_in[12];
    const float* pbp  = (const float*)d_in[13];
    const int* a_src = (const int*)d_in[14];
    const int* a_dst = (const int*)d_in[15];
    const int* i_src = (const int*)d_in[16];
    const int* i_dst = (const int*)d_in[17];
    int E = in_sizes[14];

    float* out_d = (float*)d_out;
    float* out_p = out_d + (size_t)NNODE * FEAT;

    __nv_bfloat16 *ApH, *ApL, *AdH, *AdL, *BpH, *BpL, *BdH, *BdL, *BqH, *BqL;
    float *rawd, *rawp, *hdf, *hpf, *biasP, *biasD;
    cudaGetSymbolAddress((void**)&ApH, g_Ap_hi);
    cudaGetSymbolAddress((void**)&ApL, g_Ap_lo);
    cudaGetSymbolAddress((void**)&AdH, g_Ad_hi);
    cudaGetSymbolAddress((void**)&AdL, g_Ad_lo);
    cudaGetSymbolAddress((void**)&BpH, g_Bp_hi);
    cudaGetSymbolAddress((void**)&BpL, g_Bp_lo);
    cudaGetSymbolAddress((void**)&BdH, g_Bd_hi);
    cudaGetSymbolAddress((void**)&BdL, g_Bd_lo);
    cudaGetSymbolAddress((void**)&BqH, g_Bq_hi);
    cudaGetSymbolAddress((void**)&BqL, g_Bq_lo);
    cudaGetSymbolAddress((void**)&rawd, g_rawd);
    cudaGetSymbolAddress((void**)&rawp, g_rawp);
    cudaGetSymbolAddress((void**)&hdf, g_hdf);
    cudaGetSymbolAddress((void**)&hpf, g_hpf);
    cudaGetSymbolAddress((void**)&biasP, g_biasP);
    cudaGetSymbolAddress((void**)&biasD, g_biasD);

    cudaFuncSetAttribute(mma_gemm_kernel, cudaFuncAttributeMaxDynamicSharedMemorySize, GEMM_SMEM);

    const int NW = (NNODE * FEAT + 255) / 256;
    const dim3 gg(2, (NNODE + 127) / 128);
    const dim3 g4(NNODE, 4);

    // ---- CSR build ----
    zero_cnt_kernel<<<(4 * NNODE + 255) / 256, 256>>>();
    hist_kernel<<<(4 * E + 255) / 256, 256>>>(a_src, a_dst, i_src, i_dst, E);
    scan_kernel<<<4, 1024>>>();
    fill_kernel<<<(4 * E + 255) / 256, 256>>>(a_src, a_dst, i_src, i_dst, E);

    // ---- layer 1 ----
    wprep_p_kernel<<<(FF + 255) / 256, 256>>>(Ws1, Wn1, b1);
    wprep_d_kernel<<<(FF + 255) / 256, 256>>>(Ws1, Wn1, b1);
    split_input_kernel<<<NW, 256>>>(h_p, ApH, ApL, 2048, 0);
    split_input_kernel<<<NW, 256>>>(h_d, AdH, AdL, 1024, 0);
    gather4_kernel<<<g4, 128>>>(h_d, h_p, ApH, ApL, AdH, AdL, E);
    mma_gemm_kernel<<<gg, 128, GEMM_SMEM>>>(ApH, ApL, 2048, BpH, BpL, 2048, 2048, NNODE, biasP, rawp);
    mma_gemm_kernel<<<gg, 128, GEMM_SMEM>>>(AdH, AdL, 1024, BdH, BdL, 1024, 1024, NNODE, biasD, rawd);
    zero_stats_kernel<<<1, 1024>>>();
    bn_reduce_kernel<<<dim3(2, 64), 256>>>(rawd);
    bn_norm_split_kernel<<<NW, 256>>>(rawd, hdf, AdH, AdL, 1024, gam + 0 * FEAT, bet + 0 * FEAT);
    zero_stats_kernel<<<1, 1024>>>();
    bn_reduce_kernel<<<dim3(2, 64), 256>>>(rawp);
    bn_norm_split_kernel<<<NW, 256>>>(rawp, hpf, ApH, ApL, 2048, gam + 1 * FEAT, bet + 1 * FEAT);

    // ---- layer 2 ----
    wprep_p_kernel<<<(FF + 255) / 256, 256>>>(Ws2, Wn2, b2);
    wprep_d_kernel<<<(FF + 255) / 256, 256>>>(Ws2, Wn2, b2);
    gather4_kernel<<<g4, 128>>>(hdf, hpf, ApH, ApL, AdH, AdL, E);
    mma_gemm_kernel<<<gg, 128, GEMM_SMEM>>>(ApH, ApL, 2048, BpH, BpL, 2048, 2048, NNODE, biasP, rawp);
    mma_gemm_kernel<<<gg, 128, GEMM_SMEM>>>(AdH, AdL, 1024, BdH, BdL, 1024, 1024, NNODE, biasD, rawd);
    zero_stats_kernel<<<1, 1024>>>();
    bn_reduce_kernel<<<dim3(2, 64), 256>>>(rawd);
    bn_norm_split_kernel<<<NW, 256>>>(rawd, hdf, AdH, AdL, 1024, gam + 2 * FEAT, bet + 2 * FEAT);
    zero_stats_kernel<<<1, 1024>>>();
    bn_reduce_kernel<<<dim3(2, 64), 256>>>(rawp);
    bn_norm_split_kernel<<<NW, 256>>>(rawp, hpf, ApH, ApL, 2048, gam + 3 * FEAT, bet + 3 * FEAT);

    // ---- projections ----
    wprep_q_kernel<<<(FF + 255) / 256, 256>>>(pWd, 0);
    wprep_q_kernel<<<(FF + 255) / 256, 256>>>(pWp, 1);
    mma_gemm_kernel<<<gg, 128, GEMM_SMEM>>>(AdH, AdL, 1024, BqH, BqL, 512, 512, NNODE, pbd, out_d);
    mma_gemm_kernel<<<gg, 128, GEMM_SMEM>>>(ApH, ApL, 2048, BqH + FF, BqL + FF, 512, 512, NNODE, pbp, out_p);
}

// round 5
// speedup vs baseline: 3.7967x; 1.1179x over previous
#include <cuda_runtime.h>
#include <cuda_bf16.h>
#include <cuda_fp16.h>
#include <cstdint>

#define NNODE 20000
#define MPAD  20096
#define FEAT  512
#define EMAX  320000
#define FF    (FEAT*FEAT)
#define BN_EPS 1e-5f

#if defined(__CUDA_ARCH_FEAT_SM103_ALL) || defined(__CUDA_ARCH_FEAT_SM100_ALL) || defined(__CUDA_ARCH_FEAT_SM101_ALL)
#define HAS_TCGEN05 1
#else
#define HAS_TCGEN05 0
#endif

// ================= device scratch (static, no allocs) =================
__device__ __nv_bfloat16 g_Ap_hi[(size_t)MPAD * 2048];
__device__ __nv_bfloat16 g_Ap_lo[(size_t)MPAD * 2048];
__device__ __nv_bfloat16 g_Ad_hi[(size_t)MPAD * 1024];
__device__ __nv_bfloat16 g_Ad_lo[(size_t)MPAD * 1024];
__device__ __nv_bfloat16 g_Bp_hi[512 * 2048];
__device__ __nv_bfloat16 g_Bp_lo[512 * 2048];
__device__ __nv_bfloat16 g_Bd_hi[512 * 1024];
__device__ __nv_bfloat16 g_Bd_lo[512 * 1024];
__device__ __nv_bfloat16 g_Bq_hi[2][512 * 512];
__device__ __nv_bfloat16 g_Bq_lo[2][512 * 512];
__device__ __half g_hd16[(size_t)NNODE * FEAT];   // fp16 gather sources
__device__ __half g_hp16[(size_t)NNODE * FEAT];
__device__ float g_biasP[FEAT];
__device__ float g_biasD[FEAT];
__device__ float g_rawd[(size_t)NNODE * FEAT];
__device__ float g_rawp[(size_t)NNODE * FEAT];
__device__ float g_bnstat[2 * FEAT];
__device__ int   g_cnt[4 * NNODE];
__device__ int   g_cur[4 * NNODE];
__device__ int   g_off[4 * (NNODE + 1)];
__device__ int   g_adj[4 * EMAX];

// ================= PTX helpers =================
__device__ __forceinline__ uint32_t smem_to_u32(const void* p) {
    uint32_t a;
    asm("{ .reg .u64 t; cvta.to.shared.u64 t, %1; cvt.u32.u64 %0, t; }" : "=r"(a) : "l"(p));
    return a;
}
__device__ __forceinline__ uint32_t elect_one_pred() {
    uint32_t pred;
    asm volatile("{\n\t.reg .pred p;\n\telect.sync _|p, 0xFFFFFFFF;\n\tselp.b32 %0, 1, 0, p;\n\t}" : "=r"(pred));
    return pred;
}
#define SMEM_SWIZZLE_128B(o) ((o) ^ (((o) >> 3) & 0x70))
static constexpr uint64_t SMEM_DESC_BASE_SW128 =
    (uint64_t(2) << 61) | (uint64_t(1) << 46) | (uint64_t(64) << 32) | (uint64_t(1) << 16);
#define MAKE_SMEM_DESC(base) (SMEM_DESC_BASE_SW128 | ((uint64_t)((base) >> 4) & 0x3FFF))

#define CP_ASYNC16(dst, src) \
    asm volatile("cp.async.cg.shared.global [%0], [%1], 16;" :: "r"(dst), "l"(src) : "memory")
#define CP_COMMIT() asm volatile("cp.async.commit_group;" ::: "memory")
#define CP_WAIT1() asm volatile("cp.async.wait_group 1;" ::: "memory")
#define CP_WAIT0() asm volatile("cp.async.wait_group 0;" ::: "memory")

#if HAS_TCGEN05
#define TCGEN05_ALLOC(sm, n) \
    asm volatile("tcgen05.alloc.cta_group::1.sync.aligned.shared::cta.b32 [%0], %1;" \
                 :: "r"((uint32_t)(sm)), "r"((uint32_t)(n)) : "memory")
#define TCGEN05_DEALLOC(t, n) \
    asm volatile("tcgen05.dealloc.cta_group::1.sync.aligned.b32 %0, %1;" :: "r"(t), "r"((uint32_t)(n)))
#define TCGEN05_RELINQ() \
    asm volatile("tcgen05.relinquish_alloc_permit.cta_group::1.sync.aligned;")
#define TCGEN05_COMMIT(mb) \
    asm volatile("tcgen05.commit.cta_group::1.mbarrier::arrive::one.shared::cluster.b64 [%0];" \
                 :: "r"((uint32_t)(mb)) : "memory")
#define TCGEN05_WAIT_LD()  asm volatile("tcgen05.wait::ld.sync.aligned;" ::: "memory")
#define TCGEN05_FENCE_BEFORE() asm volatile("tcgen05.fence::before_thread_sync;" ::: "memory")
#define TCGEN05_FENCE_AFTER()  asm volatile("tcgen05.fence::after_thread_sync;" ::: "memory")
#define FENCE_ASYNC_SHARED() asm volatile("fence.proxy.async.shared::cta;" ::: "memory")
#define MBARRIER_INIT(mb, c) \
    asm volatile("mbarrier.init.shared.b64 [%0], %1;" :: "r"((uint32_t)(mb)), "r"((uint32_t)(c)) : "memory")
#define MBARRIER_INVAL(mb) \
    asm volatile("mbarrier.inval.shared.b64 [%0];" :: "r"((uint32_t)(mb)) : "memory")
#define MBARRIER_WAIT_PARITY(mb, ph) do { \
    uint32_t _mb = (uint32_t)(mb), _ph = (uint32_t)(ph), _done; \
    asm volatile("{\n\t.reg .pred p;\n\tmbarrier.try_wait.parity.acquire.cta.shared::cta.b64 p, [%1], %2;\n\tselp.b32 %0, 1, 0, p;\n\t}" \
        : "=r"(_done) : "r"(_mb), "r"(_ph) : "memory"); \
    if (!_done) { \
        asm volatile("{\n\t.reg .pred P1;\n\tWL_%=: \n\tmbarrier.try_wait.parity.acquire.cta.shared::cta.b64 P1, [%0], %1, 0x989680;\n\t@P1 bra.uni WD_%=;\n\tbra.uni WL_%=;\n\tWD_%=: \n\t}" \
            :: "r"(_mb), "r"(_ph) : "memory"); \
    } \
} while (0)

#define TCGEN05_LD_X32(r, addr) \
    asm volatile("tcgen05.ld.sync.aligned.32x32b.x32.b32 " \
        "{%0, %1, %2, %3, %4, %5, %6, %7, %8, %9, %10, %11, %12, %13, %14, %15, " \
        " %16, %17, %18, %19, %20, %21, %22, %23, %24, %25, %26, %27, %28, %29, %30, %31}, [%32];" \
        : "=r"((r)[0]), "=r"((r)[1]), "=r"((r)[2]), "=r"((r)[3]), "=r"((r)[4]), "=r"((r)[5]), "=r"((r)[6]), "=r"((r)[7]), \
          "=r"((r)[8]), "=r"((r)[9]), "=r"((r)[10]), "=r"((r)[11]), "=r"((r)[12]), "=r"((r)[13]), "=r"((r)[14]), "=r"((r)[15]), \
          "=r"((r)[16]), "=r"((r)[17]), "=r"((r)[18]), "=r"((r)[19]), "=r"((r)[20]), "=r"((r)[21]), "=r"((r)[22]), "=r"((r)[23]), \
          "=r"((r)[24]), "=r"((r)[25]), "=r"((r)[26]), "=r"((r)[27]), "=r"((r)[28]), "=r"((r)[29]), "=r"((r)[30]), "=r"((r)[31]) \
        : "r"(addr))

__device__ __forceinline__ void mma_bf16_ss(uint32_t d_tmem, uint64_t a_desc, uint64_t b_desc,
                                            uint32_t idesc, uint32_t enable) {
    asm volatile(
        "{\n\t.reg .pred p;\n\tsetp.ne.u32 p, %5, 0;\n\t"
        "tcgen05.mma.cta_group::1.kind::f16 [%0], %1, %2, %3, {%4, %4, %4, %4}, p;\n\t}"
        :: "r"(d_tmem), "l"(a_desc), "l"(b_desc), "r"(idesc), "r"(0u), "r"(enable)
        : "memory");
}
#endif // HAS_TCGEN05

__device__ __forceinline__ void split1(float v, __nv_bfloat16& h, __nv_bfloat16& l) {
    h = __float2bfloat16(v);
    l = __float2bfloat16(v - __bfloat162float(h));
}

// ================= CSR build =================
__global__ void zero_cnt_kernel() {
    int i = blockIdx.x * blockDim.x + threadIdx.x;
    if (i < 4 * NNODE) g_cnt[i] = 0;
}
__global__ void hist_kernel(const int* __restrict__ a_src, const int* __restrict__ a_dst,
                            const int* __restrict__ i_src, const int* __restrict__ i_dst, int E) {
    int i = blockIdx.x * blockDim.x + threadIdx.x;
    if (i >= 4 * E) return;
    int w = i / E, e = i - w * E;
    int k = (w == 0) ? a_dst[e] : (w == 1) ? a_src[e] : (w == 2) ? i_dst[e] : i_src[e];
    atomicAdd(&g_cnt[w * NNODE + k], 1);
}
__global__ void scan_kernel() {
    int c = blockIdx.x;
    __shared__ int sh[1024];
    __shared__ int carry_sh;
    int tid = threadIdx.x;
    if (tid == 0) { carry_sh = 0; g_off[c * (NNODE + 1)] = 0; }
    __syncthreads();
    for (int base = 0; base < NNODE; base += 1024) {
        int i = base + tid;
        int v = (i < NNODE) ? g_cnt[c * NNODE + i] : 0;
        sh[tid] = v;
        __syncthreads();
        #pragma unroll
        for (int d = 1; d < 1024; d <<= 1) {
            int t = (tid >= d) ? sh[tid - d] : 0;
            __syncthreads();
            sh[tid] += t;
            __syncthreads();
        }
        int incl = sh[tid];
        int carry = carry_sh;
        __syncthreads();
        if (i < NNODE) {
            g_off[c * (NNODE + 1) + i + 1] = carry + incl;
            g_cur[c * NNODE + i] = carry + incl - v;
        }
        if (tid == 1023) carry_sh = carry + sh[1023];
        __syncthreads();
    }
}
__global__ void fill_kernel(const int* __restrict__ a_src, const int* __restrict__ a_dst,
                            const int* __restrict__ i_src, const int* __restrict__ i_dst, int E) {
    int i = blockIdx.x * blockDim.x + threadIdx.x;
    if (i >= 4 * E) return;
    int w = i / E, e = i - w * E;
    int k = (w == 0) ? a_dst[e] : (w == 1) ? a_src[e] : (w == 2) ? i_dst[e] : i_src[e];
    int v = (w == 0) ? a_src[e] : (w == 1) ? a_dst[e] : (w == 2) ? i_src[e] : i_dst[e];
    int pos = atomicAdd(&g_cur[w * NNODE + k], 1);
    g_adj[w * E + pos] = v;
}

// ========== fused 4-way segment-mean gather from fp16 sources ==========
// block: 64 threads (one node, 8 cols/thread); fp32 accumulation; bf16 hi/lo output.
__global__ void gather4_kernel(const __half* __restrict__ srcD, const __half* __restrict__ srcP,
                               __nv_bfloat16* __restrict__ ApH, __nv_bfloat16* __restrict__ ApL,
                               __nv_bfloat16* __restrict__ AdH, __nv_bfloat16* __restrict__ AdL,
                               int E) {
    int c = blockIdx.y;
    const __half* src = (c == 0) ? srcD : srcP;
    __nv_bfloat16* hi;
    __nv_bfloat16* lo;
    int lda, coff;
    if (c == 1) { hi = AdH; lo = AdL; lda = 1024; coff = 512; }
    else {
        hi = ApH; lo = ApL; lda = 2048;
        coff = (c == 0) ? 512 : (c == 2) ? 1024 : 1536;
    }
    int n = blockIdx.x;
    int t = threadIdx.x;            // 0..63, 8 halves each (16B)
    int s = g_off[c * (NNODE + 1) + n];
    int e = g_off[c * (NNODE + 1) + n + 1];
    const int* adj = g_adj + (size_t)c * E;
    float acc[8] = {0.f, 0.f, 0.f, 0.f, 0.f, 0.f, 0.f, 0.f};
    int j = s;
    for (; j + 3 < e; j += 4) {
        int r0 = adj[j], r1 = adj[j + 1], r2 = adj[j + 2], r3 = adj[j + 3];
        uint4 v0 = *(const uint4*)(src + (size_t)r0 * FEAT + t * 8);
        uint4 v1 = *(const uint4*)(src + (size_t)r1 * FEAT + t * 8);
        uint4 v2 = *(const uint4*)(src + (size_t)r2 * FEAT + t * 8);
        uint4 v3 = *(const uint4*)(src + (size_t)r3 * FEAT + t * 8);
        const uint4* vs[4] = {&v0, &v1, &v2, &v3};
        #pragma unroll
        for (int q = 0; q < 4; q++) {
            const __half2* h2 = (const __half2*)vs[q];
            #pragma unroll
            for (int p = 0; p < 4; p++) {
                float2 f = __half22float2(h2[p]);
                acc[2 * p] += f.x; acc[2 * p + 1] += f.y;
            }
        }
    }
    for (; j < e; j++) {
        int r0 = adj[j];
        uint4 v0 = *(const uint4*)(src + (size_t)r0 * FEAT + t * 8);
        const __half2* h2 = (const __half2*)&v0;
        #pragma unroll
        for (int p = 0; p < 4; p++) {
            float2 f = __half22float2(h2[p]);
            acc[2 * p] += f.x; acc[2 * p + 1] += f.y;
        }
    }
    float inv = (e > s) ? 1.0f / (float)(e - s) : 0.0f;
    __nv_bfloat16 h[8], l[8];
    #pragma unroll
    for (int q = 0; q < 8; q++) split1(acc[q] * inv, h[q], l[q]);
    size_t o = (size_t)n * lda + coff + t * 8;
    *(uint4*)(hi + o) = *(uint4*)&h[0];
    *(uint4*)(lo + o) = *(uint4*)&l[0];
}

// ========== split fp32 input into stacked-A slot + fp16 gather copy ==========
__global__ void split_input_kernel(const float* __restrict__ src,
                                   __nv_bfloat16* __restrict__ hi, __nv_bfloat16* __restrict__ lo,
                                   __half* __restrict__ f16out, int lda) {
    size_t idx = (size_t)blockIdx.x * blockDim.x + threadIdx.x;
    if (idx >= (size_t)NNODE * FEAT) return;
    int row = (int)(idx >> 9), col = (int)(idx & 511);
    float v = src[idx];
    __nv_bfloat16 h, l;
    split1(v, h, l);
    size_t o = (size_t)row * lda + col;
    hi[o] = h; lo[o] = l;
    f16out[idx] = __float2half(v);
}

// ========== weight prep: transpose + fuse + split ==========
__global__ void wprep_p_kernel(const float* __restrict__ Ws, const float* __restrict__ Wn,
                               const float* __restrict__ b) {
    int i = blockIdx.x * blockDim.x + threadIdx.x;
    if (i >= FF) return;
    int n = i & 511, k = i >> 9;
    float v0 = Ws[k * 512 + n] + Ws[2 * FF + k * 512 + n] + Ws[3 * FF + k * 512 + n];
    float v1 = Wn[0 * FF + k * 512 + n];
    float v2 = Wn[2 * FF + k * 512 + n];
    float v3 = Wn[3 * FF + k * 512 + n];
    __nv_bfloat16 h, l;
    size_t base = (size_t)n * 2048;
    split1(v0, h, l); g_Bp_hi[base + k] = h;        g_Bp_lo[base + k] = l;
    split1(v1, h, l); g_Bp_hi[base + 512 + k] = h;  g_Bp_lo[base + 512 + k] = l;
    split1(v2, h, l); g_Bp_hi[base + 1024 + k] = h; g_Bp_lo[base + 1024 + k] = l;
    split1(v3, h, l); g_Bp_hi[base + 1536 + k] = h; g_Bp_lo[base + 1536 + k] = l;
    if (i < 512) g_biasP[i] = b[i] + b[1024 + i] + b[1536 + i];
}
__global__ void wprep_d_kernel(const float* __restrict__ Ws, const float* __restrict__ Wn,
                               const float* __restrict__ b) {
    int i = blockIdx.x * blockDim.x + threadIdx.x;
    if (i >= FF) return;
    int n = i & 511, k = i >> 9;
    float v0 = Ws[FF + k * 512 + n];
    float v1 = Wn[FF + k * 512 + n];
    __nv_bfloat16 h, l;
    size_t base = (size_t)n * 1024;
    split1(v0, h, l); g_Bd_hi[base + k] = h;       g_Bd_lo[base + k] = l;
    split1(v1, h, l); g_Bd_hi[base + 512 + k] = h; g_Bd_lo[base + 512 + k] = l;
    if (i < 512) g_biasD[i] = b[512 + i];
}
__global__ void wprep_q_kernel(const float* __restrict__ W, int which) {
    int i = blockIdx.x * blockDim.x + threadIdx.x;
    if (i >= FF) return;
    int n = i & 511, k = i >> 9;
    __nv_bfloat16 h, l;
    split1(W[k * 512 + n], h, l);
    g_Bq_hi[which][n * 512 + k] = h;
    g_Bq_lo[which][n * 512 + k] = l;
}

// ================= paired pipelined tcgen05 bf16-split GEMM (blockIdx.z selects) ==========
struct GPair {
    const __nv_bfloat16 *Ah0, *Al0, *Bh0, *Bl0; const float* bias0; float* C0; int lda0, ldb0, K0;
    const __nv_bfloat16 *Ah1, *Al1, *Bh1, *Bl1; const float* bias1; float* C1; int lda1, ldb1, K1;
};
#define STAGE_BYTES (16384 + 16384 + 32768 + 32768)   // AH AL BH BL = 96KB
#define GEMM_SMEM (1024 + 2 * STAGE_BYTES)
__global__ __launch_bounds__(128)
void mma_gemm_pair(const GPair gp, int M) {
    const __nv_bfloat16* Ahi = blockIdx.z ? gp.Ah1 : gp.Ah0;
    const __nv_bfloat16* Alo = blockIdx.z ? gp.Al1 : gp.Al0;
    const __nv_bfloat16* Bhi = blockIdx.z ? gp.Bh1 : gp.Bh0;
    const __nv_bfloat16* Blo = blockIdx.z ? gp.Bl1 : gp.Bl0;
    const float* bias = blockIdx.z ? gp.bias1 : gp.bias0;
    float* C = blockIdx.z ? gp.C1 : gp.C0;
    const int lda = blockIdx.z ? gp.lda1 : gp.lda0;
    const int ldb = blockIdx.z ? gp.ldb1 : gp.ldb0;
    const int Ktot = blockIdx.z ? gp.K1 : gp.K0;
#if HAS_TCGEN05
    extern __shared__ char smem[];
    uint32_t sb = smem_to_u32(smem);
    const int tid = threadIdx.x;
    const int wid = tid >> 5, lid = tid & 31;
    const int m0 = blockIdx.y * 128, n0 = blockIdx.x * 256;

    if (wid == 0) { TCGEN05_ALLOC(sb, 256); TCGEN05_RELINQ(); }
    if (tid == 0) MBARRIER_INIT(sb + 8, 1);
    __syncthreads();
    uint32_t tbase;
    asm volatile("ld.shared.b32 %0, [%1];" : "=r"(tbase) : "r"(sb));

    const uint32_t idesc = 0x8400490u;   // F32 acc, bf16 A/B, M=128, N=256
    const int nst = Ktot >> 6;           // KC = 64

    auto issue_loads = [&](int s) {
        int k0 = s << 6;
        uint32_t base = sb + 1024 + (uint32_t)(s & 1) * STAGE_BYTES;
        #pragma unroll
        for (int c = 0; c < 8; c++) {
            int chunk = c * 128 + tid;
            int row = chunk >> 3, ch = chunk & 7;
            uint32_t sw = SMEM_SWIZZLE_128B((uint32_t)(row * 128 + ch * 16));
            size_t ga = (size_t)(m0 + row) * lda + k0 + ch * 8;
            CP_ASYNC16(base + sw, Ahi + ga);
            CP_ASYNC16(base + 16384 + sw, Alo + ga);
        }
        #pragma unroll
        for (int c = 0; c < 16; c++) {
            int chunk = c * 128 + tid;
            int row = chunk >> 3, ch = chunk & 7;
            uint32_t sw = SMEM_SWIZZLE_128B((uint32_t)(row * 128 + ch * 16));
            size_t gb = (size_t)(n0 + row) * ldb + k0 + ch * 8;
            CP_ASYNC16(base + 32768 + sw, Bhi + gb);
            CP_ASYNC16(base + 65536 + sw, Blo + gb);
        }
        CP_COMMIT();
    };

    issue_loads(0);
    for (int s = 0; s < nst; s++) {
        if (s >= 1) MBARRIER_WAIT_PARITY(sb + 8, (s - 1) & 1);
        if (s + 1 < nst) { issue_loads(s + 1); CP_WAIT1(); }
        else             { CP_WAIT0(); }
        __syncthreads();
        FENCE_ASYNC_SHARED();
        if (wid == 0 && elect_one_pred()) {
            uint32_t bufb = sb + 1024 + (uint32_t)(s & 1) * STAGE_BYTES;
            uint64_t dAh = MAKE_SMEM_DESC(bufb);
            uint64_t dAl = MAKE_SMEM_DESC(bufb + 16384);
            uint64_t dBh = MAKE_SMEM_DESC(bufb + 32768);
            uint64_t dBl = MAKE_SMEM_DESC(bufb + 65536);
            #pragma unroll
            for (int kk = 0; kk < 4; kk++) {
                uint64_t o = (uint64_t)(kk * 2);
                mma_bf16_ss(tbase, dAh + o, dBh + o, idesc, !(s == 0 && kk == 0));
                mma_bf16_ss(tbase, dAh + o, dBl + o, idesc, 1u);
                mma_bf16_ss(tbase, dAl + o, dBh + o, idesc, 1u);
            }
            TCGEN05_COMMIT(sb + 8);
        }
    }
    MBARRIER_WAIT_PARITY(sb + 8, (nst - 1) & 1);
    TCGEN05_FENCE_AFTER();

    int gr = m0 + wid * 32 + lid;
    #pragma unroll
    for (int base = 0; base < 256; base += 32) {
        uint32_t r[32];
        TCGEN05_LD_X32(r, tbase + base);
        TCGEN05_WAIT_LD();
        if (gr < M) {
            float* cp = C + (size_t)gr * 512 + n0 + base;
            #pragma unroll
            for (int j = 0; j < 32; j += 4) {
                float4 v;
                v.x = __uint_as_float(r[j + 0]) + bias[n0 + base + j + 0];
                v.y = __uint_as_float(r[j + 1]) + bias[n0 + base + j + 1];
                v.z = __uint_as_float(r[j + 2]) + bias[n0 + base + j + 2];
                v.w = __uint_as_float(r[j + 3]) + bias[n0 + base + j + 3];
                *(float4*)(cp + j) = v;
            }
        }
    }
    TCGEN05_FENCE_BEFORE();
    __syncthreads();
    if (tid == 0) MBARRIER_INVAL(sb + 8);
    __syncthreads();
    if (wid == 0) TCGEN05_DEALLOC(tbase, 256);
#else
    const int tid = threadIdx.x;
    const int m0 = blockIdx.y * 128, n0 = blockIdx.x * 256;
    for (int rc = tid; rc < 128 * 256; rc += blockDim.x) {
        int r = rc >> 8, c = rc & 255;
        int gr = m0 + r, gc = n0 + c;
        if (gr >= M) continue;
        const __nv_bfloat16* ah = Ahi + (size_t)gr * lda;
        const __nv_bfloat16* al = Alo + (size_t)gr * lda;
        const __nv_bfloat16* bh = Bhi + (size_t)gc * ldb;
        const __nv_bfloat16* bl = Blo + (size_t)gc * ldb;
        float acc = 0.f;
        for (int k = 0; k < Ktot; k++) {
            float ahv = __bfloat162float(ah[k]), alv = __bfloat162float(al[k]);
            float bhv = __bfloat162float(bh[k]), blv = __bfloat162float(bl[k]);
            acc += ahv * bhv + ahv * blv + alv * bhv;
        }
        C[(size_t)gr * 512 + gc] = acc + bias[gc];
    }
#endif
}

// ================= BatchNorm + ReLU =================
__global__ void zero_stats_kernel() {
    int i = threadIdx.x;
    if (i < 2 * FEAT) g_bnstat[i] = 0.f;
}
__global__ void bn_reduce_kernel(const float* __restrict__ x) {
    int col = blockIdx.x * 256 + threadIdx.x;   // grid.x = 2
    float s = 0.f, s2 = 0.f;
    for (int r = blockIdx.y; r < NNODE; r += gridDim.y) {
        float v = x[(size_t)r * FEAT + col];
        s += v; s2 += v * v;
    }
    atomicAdd(&g_bnstat[col], s);
    atomicAdd(&g_bnstat[FEAT + col], s2);
}
// normalize + relu; write bf16 hi/lo self slot + fp16 gather copy
__global__ void bn_norm_split_kernel(const float* __restrict__ raw, __half* __restrict__ f16out,
                                     __nv_bfloat16* __restrict__ hi, __nv_bfloat16* __restrict__ lo,
                                     int lda,
                                     const float* __restrict__ gamma, const float* __restrict__ beta) {
    size_t idx = (size_t)blockIdx.x * blockDim.x + threadIdx.x;
    if (idx >= (size_t)NNODE * FEAT) return;
    int col = (int)(idx & (FEAT - 1));
    int row = (int)(idx >> 9);
    float mean = g_bnstat[col] * (1.0f / NNODE);
    float var  = g_bnstat[FEAT + col] * (1.0f / NNODE) - mean * mean;
    float sc = gamma[col] * rsqrtf(var + BN_EPS);
    float v = (raw[idx] - mean) * sc + beta[col];
    v = v > 0.f ? v : 0.f;
    f16out[idx] = __float2half(v);
    __nv_bfloat16 h, l;
    split1(v, h, l);
    size_t o = (size_t)row * lda + col;
    hi[o] = h; lo[o] = l;
}

// ================= host orchestration =================
extern "C" void kernel_launch(void* const* d_in, const int* in_sizes, int n_in,
                              void* d_out, int out_size) {
    const float* h_d  = (const float*)d_in[0];
    const float* h_p  = (const float*)d_in[1];
    const float* Ws1  = (const float*)d_in[2];
    const float* Wn1  = (const float*)d_in[3];
    const float* b1   = (const float*)d_in[4];
    const float* Ws2  = (const float*)d_in[5];
    const float* Wn2  = (const float*)d_in[6];
    const float* b2   = (const float*)d_in[7];
    const float* gam  = (const float*)d_in[8];
    const float* bet  = (const float*)d_in[9];
    const float* pWd  = (const float*)d_in[10];
    const float* pbd  = (const float*)d_in[11];
    const float* pWp  = (const float*)d_in[12];
    const float* pbp  = (const float*)d_in[13];
    const int* a_src = (const int*)d_in[14];
    const int* a_dst = (const int*)d_in[15];
    const int* i_src = (const int*)d_in[16];
    const int* i_dst = (const int*)d_in[17];
    int E = in_sizes[14];

    float* out_d = (float*)d_out;
    float* out_p = out_d + (size_t)NNODE * FEAT;

    __nv_bfloat16 *ApH, *ApL, *AdH, *AdL, *BpH, *BpL, *BdH, *BdL, *BqH, *BqL;
    float *rawd, *rawp, *biasP, *biasD;
    __half *hd16, *hp16;
    cudaGetSymbolAddress((void**)&ApH, g_Ap_hi);
    cudaGetSymbolAddress((void**)&ApL, g_Ap_lo);
    cudaGetSymbolAddress((void**)&AdH, g_Ad_hi);
    cudaGetSymbolAddress((void**)&AdL, g_Ad_lo);
    cudaGetSymbolAddress((void**)&BpH, g_Bp_hi);
    cudaGetSymbolAddress((void**)&BpL, g_Bp_lo);
    cudaGetSymbolAddress((void**)&BdH, g_Bd_hi);
    cudaGetSymbolAddress((void**)&BdL, g_Bd_lo);
    cudaGetSymbolAddress((void**)&BqH, g_Bq_hi);
    cudaGetSymbolAddress((void**)&BqL, g_Bq_lo);
    cudaGetSymbolAddress((void**)&rawd, g_rawd);
    cudaGetSymbolAddress((void**)&rawp, g_rawp);
    cudaGetSymbolAddress((void**)&biasP, g_biasP);
    cudaGetSymbolAddress((void**)&biasD, g_biasD);
    cudaGetSymbolAddress((void**)&hd16, g_hd16);
    cudaGetSymbolAddress((void**)&hp16, g_hp16);

    cudaFuncSetAttribute(mma_gemm_pair, cudaFuncAttributeMaxDynamicSharedMemorySize, GEMM_SMEM);

    const int NW = (NNODE * FEAT + 255) / 256;
    const dim3 gpair(2, (NNODE + 127) / 128, 2);
    const dim3 g4(NNODE, 4);

    GPair lay;   // z=0: protein (K=2048), z=1: disease (K=1024)
    lay.Ah0 = ApH; lay.Al0 = ApL; lay.Bh0 = BpH; lay.Bl0 = BpL;
    lay.bias0 = biasP; lay.C0 = rawp; lay.lda0 = 2048; lay.ldb0 = 2048; lay.K0 = 2048;
    lay.Ah1 = AdH; lay.Al1 = AdL; lay.Bh1 = BdH; lay.Bl1 = BdL;
    lay.bias1 = biasD; lay.C1 = rawd; lay.lda1 = 1024; lay.ldb1 = 1024; lay.K1 = 1024;

    GPair proj;  // z=0: disease proj, z=1: protein proj (K=512 both)
    proj.Ah0 = AdH; proj.Al0 = AdL; proj.Bh0 = BqH; proj.Bl0 = BqL;
    proj.bias0 = pbd; proj.C0 = out_d; proj.lda0 = 1024; proj.ldb0 = 512; proj.K0 = 512;
    proj.Ah1 = ApH; proj.Al1 = ApL; proj.Bh1 = BqH + FF; proj.Bl1 = BqL + FF;
    proj.bias1 = pbp; proj.C1 = out_p; proj.lda1 = 2048; proj.ldb1 = 512; proj.K1 = 512;

    // ---- CSR build ----
    zero_cnt_kernel<<<(4 * NNODE + 255) / 256, 256>>>();
    hist_kernel<<<(4 * E + 255) / 256, 256>>>(a_src, a_dst, i_src, i_dst, E);
    scan_kernel<<<4, 1024>>>();
    fill_kernel<<<(4 * E + 255) / 256, 256>>>(a_src, a_dst, i_src, i_dst, E);

    // ---- layer 1 ----
    wprep_p_kernel<<<(FF + 255) / 256, 256>>>(Ws1, Wn1, b1);
    wprep_d_kernel<<<(FF + 255) / 256, 256>>>(Ws1, Wn1, b1);
    split_input_kernel<<<NW, 256>>>(h_p, ApH, ApL, hp16, 2048);
    split_input_kernel<<<NW, 256>>>(h_d, AdH, AdL, hd16, 1024);
    gather4_kernel<<<g4, 64>>>(hd16, hp16, ApH, ApL, AdH, AdL, E);
    mma_gemm_pair<<<gpair, 128, GEMM_SMEM>>>(lay, NNODE);
    zero_stats_kernel<<<1, 1024>>>();
    bn_reduce_kernel<<<dim3(2, 64), 256>>>(rawd);
    bn_norm_split_kernel<<<NW, 256>>>(rawd, hd16, AdH, AdL, 1024, gam + 0 * FEAT, bet + 0 * FEAT);
    zero_stats_kernel<<<1, 1024>>>();
    bn_reduce_kernel<<<dim3(2, 64), 256>>>(rawp);
    bn_norm_split_kernel<<<NW, 256>>>(rawp, hp16, ApH, ApL, 2048, gam + 1 * FEAT, bet + 1 * FEAT);

    // ---- layer 2 ----
    wprep_p_kernel<<<(FF + 255) / 256, 256>>>(Ws2, Wn2, b2);
    wprep_d_kernel<<<(FF + 255) / 256, 256>>>(Ws2, Wn2, b2);
    gather4_kernel<<<g4, 64>>>(hd16, hp16, ApH, ApL, AdH, AdL, E);
    mma_gemm_pair<<<gpair, 128, GEMM_SMEM>>>(lay, NNODE);
    zero_stats_kernel<<<1, 1024>>>();
    bn_reduce_kernel<<<dim3(2, 64), 256>>>(rawd);
    bn_norm_split_kernel<<<NW, 256>>>(rawd, hd16, AdH, AdL, 1024, gam + 2 * FEAT, bet + 2 * FEAT);
    zero_stats_kernel<<<1, 1024>>>();
    bn_reduce_kernel<<<dim3(2, 64), 256>>>(rawp);
    bn_norm_split_kernel<<<NW, 256>>>(rawp, hp16, ApH, ApL, 2048, gam + 3 * FEAT, bet + 3 * FEAT);

    // ---- projections ----
    wprep_q_kernel<<<(FF + 255) / 256, 256>>>(pWd, 0);
    wprep_q_kernel<<<(FF + 255) / 256, 256>>>(pWp, 1);
    mma_gemm_pair<<<gpair, 128, GEMM_SMEM>>>(proj, NNODE);
}